// round 1
// baseline (speedup 1.0000x reference)
#include <cuda_runtime.h>
#include <math.h>
#include <stdint.h>

#define D_MODEL 1024
#define HEADS   16
#define DKH     64
#define D_FF    4096
#define BATCH   2
#define SEQ     2048
#define MROWS   (BATCH * SEQ)   // 4096
#define EPS_LN  1e-6f

// ---------------- scratch (static device globals; no allocs) ----------------
__device__ float g_q[MROWS * D_MODEL];
__device__ float g_k[MROWS * D_MODEL];
__device__ float g_v[MROWS * D_MODEL];
__device__ float g_attn[MROWS * D_MODEL];
__device__ float g_tmp[MROWS * D_MODEL];
__device__ float g_r1[MROWS * D_MODEL];
__device__ float g_ff[MROWS * D_FF];
__device__ float g_tmp2[MROWS * D_MODEL];

// ---------------- SGEMM: C = A @ B^T (+ epilogue) ---------------------------
// A: [M,K] row-major, B: [N,K] row-major, C: [M,N]
// EPI: 0 = none, 1 = relu, 2 = residual add (C = R + A@B^T)
#define BM 128
#define BN 128
#define BK 16

template <int EPI>
__global__ __launch_bounds__(256, 2)
void sgemm_tn(const float* __restrict__ A, const float* __restrict__ B,
              const float* __restrict__ R, float* __restrict__ C,
              int M, int N, int K)
{
    __shared__ __align__(16) float As[BK][BM];
    __shared__ __align__(16) float Bs[BK][BN];

    const int tid = threadIdx.x;
    const int tx = tid & 15;        // 0..15 -> N
    const int ty = tid >> 4;        // 0..15 -> M

    const float* Ab = A + (size_t)blockIdx.y * BM * K;
    const float* Bb = B + (size_t)blockIdx.x * BN * K;

    float acc[8][8];
#pragma unroll
    for (int i = 0; i < 8; i++)
#pragma unroll
        for (int j = 0; j < 8; j++) acc[i][j] = 0.f;

    for (int k0 = 0; k0 < K; k0 += BK) {
        // load A tile: 128x16 = 512 float4, 256 threads -> 2 each
#pragma unroll
        for (int it = 0; it < 2; it++) {
            int idx = tid + it * 256;
            int r  = idx >> 2;
            int c4 = (idx & 3) << 2;
            float4 v = *(const float4*)(Ab + (size_t)r * K + k0 + c4);
            As[c4 + 0][r] = v.x; As[c4 + 1][r] = v.y;
            As[c4 + 2][r] = v.z; As[c4 + 3][r] = v.w;
        }
        // load B tile (rows of B are columns of B^T)
#pragma unroll
        for (int it = 0; it < 2; it++) {
            int idx = tid + it * 256;
            int r  = idx >> 2;
            int c4 = (idx & 3) << 2;
            float4 v = *(const float4*)(Bb + (size_t)r * K + k0 + c4);
            Bs[c4 + 0][r] = v.x; Bs[c4 + 1][r] = v.y;
            Bs[c4 + 2][r] = v.z; Bs[c4 + 3][r] = v.w;
        }
        __syncthreads();

#pragma unroll
        for (int k = 0; k < BK; k++) {
            float4 a0 = *(const float4*)&As[k][ty * 8];
            float4 a1 = *(const float4*)&As[k][ty * 8 + 4];
            float4 b0 = *(const float4*)&Bs[k][tx * 8];
            float4 b1 = *(const float4*)&Bs[k][tx * 8 + 4];
            float ra[8] = {a0.x, a0.y, a0.z, a0.w, a1.x, a1.y, a1.z, a1.w};
            float rb[8] = {b0.x, b0.y, b0.z, b0.w, b1.x, b1.y, b1.z, b1.w};
#pragma unroll
            for (int i = 0; i < 8; i++)
#pragma unroll
                for (int j = 0; j < 8; j++) acc[i][j] = fmaf(ra[i], rb[j], acc[i][j]);
        }
        __syncthreads();
    }

    const int row0 = blockIdx.y * BM + ty * 8;
    const int col0 = blockIdx.x * BN + tx * 8;
#pragma unroll
    for (int i = 0; i < 8; i++) {
        size_t roff = (size_t)(row0 + i) * N + col0;
#pragma unroll
        for (int j = 0; j < 8; j++) {
            float v = acc[i][j];
            if (EPI == 1) v = fmaxf(v, 0.f);
            if (EPI == 2) v += R[roff + j];
            C[roff + j] = v;
        }
    }
}

// ---------------- Flash attention (fp32, causal) ----------------------------
// grid: (SEQ/64, HEADS, BATCH), 256 threads. Layouts: [B, S, H*DKH]
__global__ __launch_bounds__(256, 1)
void flash_attn(const float* __restrict__ Q, const float* __restrict__ Kg,
                const float* __restrict__ V, float* __restrict__ O)
{
    extern __shared__ float sm[];
    float* Qs   = sm;                    // 64*64
    float* Ks   = Qs + 64 * 64;          // 64*65 (padded)
    float* Vs   = Ks + 64 * 65;          // 64*65 (padded)
    float* Ss   = Vs + 64 * 65;          // 64*64
    float* mrow = Ss + 64 * 64;          // 64
    float* lrow = mrow + 64;             // 64
    float* crow = lrow + 64;             // 64

    const int qb = blockIdx.x, h = blockIdx.y, bb = blockIdx.z;
    const int tid = threadIdx.x;
    const int tx = tid & 15, ty = tid >> 4;
    const int q0 = qb * 64;
    const size_t base = (size_t)bb * SEQ * D_MODEL + (size_t)h * DKH;

    // load Q block (64x64)
#pragma unroll
    for (int it = 0; it < 4; it++) {
        int idx = tid + it * 256;
        int r = idx >> 4;
        int c = (idx & 15) << 2;
        float4 v = *(const float4*)(Q + base + (size_t)(q0 + r) * D_MODEL + c);
        *(float4*)(Qs + r * 64 + c) = v;
    }
    if (tid < 64) { mrow[tid] = -INFINITY; lrow[tid] = 0.f; }

    float accO[4][4];
#pragma unroll
    for (int i = 0; i < 4; i++)
#pragma unroll
        for (int j = 0; j < 4; j++) accO[i][j] = 0.f;

    __syncthreads();

    for (int kb = 0; kb <= qb; kb++) {
        const int k0 = kb * 64;
        // load K, V blocks
#pragma unroll
        for (int it = 0; it < 4; it++) {
            int idx = tid + it * 256;
            int r = idx >> 4;
            int c = (idx & 15) << 2;
            float4 kv = *(const float4*)(Kg + base + (size_t)(k0 + r) * D_MODEL + c);
            Ks[r * 65 + c + 0] = kv.x; Ks[r * 65 + c + 1] = kv.y;
            Ks[r * 65 + c + 2] = kv.z; Ks[r * 65 + c + 3] = kv.w;
            float4 vv = *(const float4*)(V + base + (size_t)(k0 + r) * D_MODEL + c);
            Vs[r * 65 + c + 0] = vv.x; Vs[r * 65 + c + 1] = vv.y;
            Vs[r * 65 + c + 2] = vv.z; Vs[r * 65 + c + 3] = vv.w;
        }
        __syncthreads();

        // S = Q K^T * 1/sqrt(dk)
        float s[4][4];
#pragma unroll
        for (int i = 0; i < 4; i++)
#pragma unroll
            for (int j = 0; j < 4; j++) s[i][j] = 0.f;

#pragma unroll 4
        for (int k = 0; k < 64; k++) {
            float ra[4], rb[4];
#pragma unroll
            for (int i = 0; i < 4; i++) ra[i] = Qs[(ty * 4 + i) * 64 + k];
#pragma unroll
            for (int j = 0; j < 4; j++) rb[j] = Ks[(tx * 4 + j) * 65 + k];
#pragma unroll
            for (int i = 0; i < 4; i++)
#pragma unroll
                for (int j = 0; j < 4; j++) s[i][j] = fmaf(ra[i], rb[j], s[i][j]);
        }
        const bool diag = (kb == qb);
#pragma unroll
        for (int i = 0; i < 4; i++) {
#pragma unroll
            for (int j = 0; j < 4; j++) {
                float v = s[i][j] * 0.125f;
                if (diag && (tx * 4 + j) > (ty * 4 + i)) v = -INFINITY;
                Ss[(ty * 4 + i) * 64 + tx * 4 + j] = v;
            }
        }
        __syncthreads();

        // online softmax row update (one thread per row)
        if (tid < 64) {
            const int r = tid;
            float mold = mrow[r];
            float mx = mold;
#pragma unroll 8
            for (int c = 0; c < 64; c++) mx = fmaxf(mx, Ss[r * 64 + c]);
            float corr = __expf(mold - mx);
            float sum = 0.f;
#pragma unroll 8
            for (int c = 0; c < 64; c++) {
                float p = __expf(Ss[r * 64 + c] - mx);
                Ss[r * 64 + c] = p;
                sum += p;
            }
            mrow[r] = mx;
            lrow[r] = lrow[r] * corr + sum;
            crow[r] = corr;
        }
        __syncthreads();

        // O = O*corr + P @ V
#pragma unroll
        for (int i = 0; i < 4; i++) {
            float c0 = crow[ty * 4 + i];
#pragma unroll
            for (int j = 0; j < 4; j++) accO[i][j] *= c0;
        }
#pragma unroll 4
        for (int k = 0; k < 64; k++) {
            float pv[4], vv[4];
#pragma unroll
            for (int i = 0; i < 4; i++) pv[i] = Ss[(ty * 4 + i) * 64 + k];
#pragma unroll
            for (int j = 0; j < 4; j++) vv[j] = Vs[k * 65 + tx * 4 + j];
#pragma unroll
            for (int i = 0; i < 4; i++)
#pragma unroll
                for (int j = 0; j < 4; j++) accO[i][j] = fmaf(pv[i], vv[j], accO[i][j]);
        }
        __syncthreads();
    }

    // normalize + store
#pragma unroll
    for (int i = 0; i < 4; i++) {
        const int r = ty * 4 + i;
        const float inv = 1.f / lrow[r];
#pragma unroll
        for (int j = 0; j < 4; j++) {
            O[base + (size_t)(q0 + r) * D_MODEL + tx * 4 + j] = accO[i][j] * inv;
        }
    }
}

// ---------------- LayerNorm (ddof=1, torch-style) ----------------------------
// one block per row of 1024, 256 threads x float4
__global__ __launch_bounds__(256)
void layernorm_k(const float* __restrict__ in, const float* __restrict__ gamma,
                 const float* __restrict__ beta, float* __restrict__ out)
{
    const int row = blockIdx.x;
    const int tid = threadIdx.x;
    const float4 v = ((const float4*)(in + (size_t)row * D_MODEL))[tid];
    float s  = v.x + v.y + v.z + v.w;
    float ss = v.x * v.x + v.y * v.y + v.z * v.z + v.w * v.w;

    __shared__ float rs[8], rss[8];
#pragma unroll
    for (int o = 16; o > 0; o >>= 1) {
        s  += __shfl_down_sync(0xFFFFFFFFu, s, o);
        ss += __shfl_down_sync(0xFFFFFFFFu, ss, o);
    }
    if ((tid & 31) == 0) { rs[tid >> 5] = s; rss[tid >> 5] = ss; }
    __syncthreads();
    float S = 0.f, SS = 0.f;
#pragma unroll
    for (int i = 0; i < 8; i++) { S += rs[i]; SS += rss[i]; }

    const float mean = S * (1.f / (float)D_MODEL);
    const float var  = (SS - (float)D_MODEL * mean * mean) * (1.f / (float)(D_MODEL - 1));
    const float inv  = rsqrtf(var + EPS_LN);

    const float4 g = ((const float4*)gamma)[tid];
    const float4 b = ((const float4*)beta)[tid];
    float4 o;
    o.x = g.x * (v.x - mean) * inv + b.x;
    o.y = g.y * (v.y - mean) * inv + b.y;
    o.z = g.z * (v.z - mean) * inv + b.z;
    o.w = g.w * (v.w - mean) * inv + b.w;
    ((float4*)(out + (size_t)row * D_MODEL))[tid] = o;
}

// ---------------- host launcher ---------------------------------------------
extern "C" void kernel_launch(void* const* d_in, const int* in_sizes, int n_in,
                              void* d_out, int out_size)
{
    (void)in_sizes; (void)n_in; (void)out_size;
    const float* x  = (const float*)d_in[0];
    // d_in[1] = mask (causal; implied)
    const float* Wq = (const float*)d_in[2];
    const float* Wk = (const float*)d_in[3];
    const float* Wv = (const float*)d_in[4];
    const float* Wo = (const float*)d_in[5];
    const float* W1 = (const float*)d_in[6];
    const float* W2 = (const float*)d_in[7];
    const float* g1 = (const float*)d_in[8];
    const float* b1 = (const float*)d_in[9];
    const float* g2 = (const float*)d_in[10];
    const float* b2 = (const float*)d_in[11];
    float* out = (float*)d_out;

    float *q, *k, *v, *attn, *tmp, *r1, *ff, *tmp2;
    cudaGetSymbolAddress((void**)&q,    g_q);
    cudaGetSymbolAddress((void**)&k,    g_k);
    cudaGetSymbolAddress((void**)&v,    g_v);
    cudaGetSymbolAddress((void**)&attn, g_attn);
    cudaGetSymbolAddress((void**)&tmp,  g_tmp);
    cudaGetSymbolAddress((void**)&r1,   g_r1);
    cudaGetSymbolAddress((void**)&ff,   g_ff);
    cudaGetSymbolAddress((void**)&tmp2, g_tmp2);

    const dim3 blk(256);
    const dim3 gD(D_MODEL / BN, MROWS / BM);   // (8, 32)
    const dim3 gF(D_FF / BN, MROWS / BM);      // (32, 32)

    // QKV projections
    sgemm_tn<0><<<gD, blk>>>(x, Wq, nullptr, q, MROWS, D_MODEL, D_MODEL);
    sgemm_tn<0><<<gD, blk>>>(x, Wk, nullptr, k, MROWS, D_MODEL, D_MODEL);
    sgemm_tn<0><<<gD, blk>>>(x, Wv, nullptr, v, MROWS, D_MODEL, D_MODEL);

    // Flash attention
    const int smem = (64 * 64 + 2 * 64 * 65 + 64 * 64 + 3 * 64) * (int)sizeof(float); // 66816 B
    cudaFuncSetAttribute(flash_attn, cudaFuncAttributeMaxDynamicSharedMemorySize, smem);
    flash_attn<<<dim3(SEQ / 64, HEADS, BATCH), blk, smem>>>(q, k, v, attn);

    // Output projection + residual, then LN1
    sgemm_tn<2><<<gD, blk>>>(attn, Wo, x, tmp, MROWS, D_MODEL, D_MODEL);
    layernorm_k<<<MROWS, blk>>>(tmp, g1, b1, r1);

    // FFN
    sgemm_tn<1><<<gF, blk>>>(r1, W1, nullptr, ff, MROWS, D_FF, D_MODEL);
    sgemm_tn<2><<<gD, blk>>>(ff, W2, r1, tmp2, MROWS, D_MODEL, D_FF);
    layernorm_k<<<MROWS, blk>>>(tmp2, g2, b2, out);
}

// round 3
// speedup vs baseline: 1.6056x; 1.6056x over previous
#include <cuda_runtime.h>
#include <cuda_bf16.h>
#include <mma.h>
#include <math.h>
#include <stdint.h>

using namespace nvcuda;

#define D_MODEL 1024
#define HEADS   16
#define DKH     64
#define D_FF    4096
#define BATCH   2
#define SEQ     2048
#define MROWS   (BATCH * SEQ)   // 4096
#define EPS_LN  1e-6f

// ---------------- scratch (static device globals; no allocs) ----------------
__device__ float g_q[MROWS * D_MODEL];
__device__ float g_k[MROWS * D_MODEL];
__device__ float g_v[MROWS * D_MODEL];
__device__ float g_attn[MROWS * D_MODEL];
__device__ float g_tmp[MROWS * D_MODEL];
__device__ float g_r1[MROWS * D_MODEL];
__device__ float g_ff[MROWS * D_FF];
__device__ float g_tmp2[MROWS * D_MODEL];

// ================= bf16 split helpers =======================================
__device__ __forceinline__ void split2(float a, float b, uint32_t& hi, uint32_t& lo) {
    __nv_bfloat16 ha = __float2bfloat16_rn(a);
    __nv_bfloat16 hb = __float2bfloat16_rn(b);
    float la = a - __bfloat162float(ha);
    float lb = b - __bfloat162float(hb);
    __nv_bfloat162 hv = __halves2bfloat162(ha, hb);
    __nv_bfloat162 lv = __floats2bfloat162_rn(la, lb);
    hi = *reinterpret_cast<uint32_t*>(&hv);
    lo = *reinterpret_cast<uint32_t*>(&lv);
}

// ================= WMMA GEMM: C = A @ B^T (+epilogue), bf16x3 ================
// A:[M,K] rm, B:[N,K] rm, C:[M,N]. EPI: 0 none, 1 relu, 2 residual (C = R + AB^T)
// block tile 128x128, BK=32, 8 warps (2 m x 4 n), warp tile 32x64.
#define WBK   32
#define LDT   40                        // smem row stride (bf16 elems), conflict pad
#define TILE_E (128 * LDT)              // 5120 elems per tile
#define STAGE_E (4 * TILE_E)            // A_hi, A_lo, B_hi, B_lo
#define GEMM_SMEM (2 * STAGE_E * (int)sizeof(__nv_bfloat16))   // 81920 B

__device__ __forceinline__ void cvt_store(__nv_bfloat16* hi, __nv_bfloat16* lo,
                                          int r, int c4, float4 v) {
    uint32_t h01, l01, h23, l23;
    split2(v.x, v.y, h01, l01);
    split2(v.z, v.w, h23, l23);
    *(uint2*)(hi + r * LDT + c4) = make_uint2(h01, h23);
    *(uint2*)(lo + r * LDT + c4) = make_uint2(l01, l23);
}

template <int EPI>
__global__ __launch_bounds__(256)
void gemm_wmma(const float* __restrict__ A, const float* __restrict__ B,
               const float* __restrict__ R, float* __restrict__ C,
               int M, int N, int K)
{
    extern __shared__ __nv_bfloat16 sh[];

    const int tid = threadIdx.x;
    const int wid = tid >> 5;
    const int wm = (wid & 3) * 32;       // warp m offset in tile
    const int wn = (wid >> 2) * 64;      // warp n offset in tile

    const int row0 = blockIdx.y * 128;
    const int col0 = blockIdx.x * 128;
    const float* Ab = A + (size_t)row0 * K;
    const float* Bb = B + (size_t)col0 * K;

    wmma::fragment<wmma::accumulator, 16, 16, 16, float> acc[2][4];
#pragma unroll
    for (int i = 0; i < 2; i++)
#pragma unroll
        for (int j = 0; j < 4; j++) wmma::fill_fragment(acc[i][j], 0.f);

    // per-thread load coords: 1024 float4 per 128x32 fp32 tile -> 4 each
    const int lr = tid >> 3;             // row (0..31 per it step of 32 rows)
    const int lc4 = (tid & 7) << 2;      // col (float idx, 0..28)

    float4 ar[4], br[4];
    // ---- preload tile 0 ----
#pragma unroll
    for (int it = 0; it < 4; it++) {
        int r = lr + it * 32;
        ar[it] = *(const float4*)(Ab + (size_t)r * K + lc4);
        br[it] = *(const float4*)(Bb + (size_t)r * K + lc4);
    }
    {
        __nv_bfloat16* Ah = sh;
        __nv_bfloat16* Al = Ah + TILE_E;
        __nv_bfloat16* Bh = Al + TILE_E;
        __nv_bfloat16* Bl = Bh + TILE_E;
#pragma unroll
        for (int it = 0; it < 4; it++) {
            int r = lr + it * 32;
            cvt_store(Ah, Al, r, lc4, ar[it]);
            cvt_store(Bh, Bl, r, lc4, br[it]);
        }
    }
    __syncthreads();

    const int T = K / WBK;
    for (int t = 0; t < T; t++) {
        const int cur = t & 1;
        const int nxt = cur ^ 1;

        if (t + 1 < T) {
            const int k0 = (t + 1) * WBK;
#pragma unroll
            for (int it = 0; it < 4; it++) {
                int r = lr + it * 32;
                ar[it] = *(const float4*)(Ab + (size_t)r * K + k0 + lc4);
                br[it] = *(const float4*)(Bb + (size_t)r * K + k0 + lc4);
            }
        }

        // ---- compute on stage cur ----
        {
            __nv_bfloat16* Ah = sh + cur * STAGE_E;
            __nv_bfloat16* Al = Ah + TILE_E;
            __nv_bfloat16* Bh = Al + TILE_E;
            __nv_bfloat16* Bl = Bh + TILE_E;
#pragma unroll
            for (int ks = 0; ks < WBK; ks += 16) {
                wmma::fragment<wmma::matrix_a, 16, 16, 16, __nv_bfloat16, wmma::row_major> a_hi[2], a_lo[2];
                wmma::fragment<wmma::matrix_b, 16, 16, 16, __nv_bfloat16, wmma::col_major> b_hi[4], b_lo[4];
#pragma unroll
                for (int i = 0; i < 2; i++) {
                    wmma::load_matrix_sync(a_hi[i], Ah + (wm + i * 16) * LDT + ks, LDT);
                    wmma::load_matrix_sync(a_lo[i], Al + (wm + i * 16) * LDT + ks, LDT);
                }
#pragma unroll
                for (int j = 0; j < 4; j++) {
                    wmma::load_matrix_sync(b_hi[j], Bh + (wn + j * 16) * LDT + ks, LDT);
                    wmma::load_matrix_sync(b_lo[j], Bl + (wn + j * 16) * LDT + ks, LDT);
                }
#pragma unroll
                for (int i = 0; i < 2; i++) {
#pragma unroll
                    for (int j = 0; j < 4; j++) {
                        wmma::mma_sync(acc[i][j], a_hi[i], b_hi[j], acc[i][j]);
                        wmma::mma_sync(acc[i][j], a_hi[i], b_lo[j], acc[i][j]);
                        wmma::mma_sync(acc[i][j], a_lo[i], b_hi[j], acc[i][j]);
                    }
                }
            }
        }

        if (t + 1 < T) {
            __nv_bfloat16* Ah = sh + nxt * STAGE_E;
            __nv_bfloat16* Al = Ah + TILE_E;
            __nv_bfloat16* Bh = Al + TILE_E;
            __nv_bfloat16* Bl = Bh + TILE_E;
#pragma unroll
            for (int it = 0; it < 4; it++) {
                int r = lr + it * 32;
                cvt_store(Ah, Al, r, lc4, ar[it]);
                cvt_store(Bh, Bl, r, lc4, br[it]);
            }
        }
        __syncthreads();
    }

    // ---- epilogue ----
#pragma unroll
    for (int i = 0; i < 2; i++) {
#pragma unroll
        for (int j = 0; j < 4; j++) {
            const int row = row0 + wm + i * 16;
            const int col = col0 + wn + j * 16;
            float* cptr = C + (size_t)row * N + col;
            if (EPI == 2) {
                wmma::fragment<wmma::accumulator, 16, 16, 16, float> rf;
                wmma::load_matrix_sync(rf, R + (size_t)row * N + col, N, wmma::mem_row_major);
#pragma unroll
                for (int e = 0; e < rf.num_elements; e++) acc[i][j].x[e] += rf.x[e];
            }
            if (EPI == 1) {
#pragma unroll
                for (int e = 0; e < acc[i][j].num_elements; e++)
                    acc[i][j].x[e] = fmaxf(acc[i][j].x[e], 0.f);
            }
            wmma::store_matrix_sync(cptr, acc[i][j], N, wmma::mem_row_major);
        }
    }
}

// ---------------- Flash attention (fp32, causal) ----------------------------
// grid: (SEQ/64, HEADS, BATCH), 256 threads. Layouts: [B, S, H*DKH]
__global__ __launch_bounds__(256, 1)
void flash_attn(const float* __restrict__ Q, const float* __restrict__ Kg,
                const float* __restrict__ V, float* __restrict__ O)
{
    extern __shared__ float sm[];
    float* Qs   = sm;                    // 64*64
    float* Ks   = Qs + 64 * 64;          // 64*65 (padded)
    float* Vs   = Ks + 64 * 65;          // 64*65 (padded)
    float* Ss   = Vs + 64 * 65;          // 64*64
    float* mrow = Ss + 64 * 64;          // 64
    float* lrow = mrow + 64;             // 64
    float* crow = lrow + 64;             // 64

    const int qb = blockIdx.x, h = blockIdx.y, bb = blockIdx.z;
    const int tid = threadIdx.x;
    const int tx = tid & 15, ty = tid >> 4;
    const int q0 = qb * 64;
    const size_t base = (size_t)bb * SEQ * D_MODEL + (size_t)h * DKH;

#pragma unroll
    for (int it = 0; it < 4; it++) {
        int idx = tid + it * 256;
        int r = idx >> 4;
        int c = (idx & 15) << 2;
        float4 v = *(const float4*)(Q + base + (size_t)(q0 + r) * D_MODEL + c);
        *(float4*)(Qs + r * 64 + c) = v;
    }
    if (tid < 64) { mrow[tid] = -INFINITY; lrow[tid] = 0.f; }

    float accO[4][4];
#pragma unroll
    for (int i = 0; i < 4; i++)
#pragma unroll
        for (int j = 0; j < 4; j++) accO[i][j] = 0.f;

    __syncthreads();

    for (int kb = 0; kb <= qb; kb++) {
        const int k0 = kb * 64;
#pragma unroll
        for (int it = 0; it < 4; it++) {
            int idx = tid + it * 256;
            int r = idx >> 4;
            int c = (idx & 15) << 2;
            float4 kv = *(const float4*)(Kg + base + (size_t)(k0 + r) * D_MODEL + c);
            Ks[r * 65 + c + 0] = kv.x; Ks[r * 65 + c + 1] = kv.y;
            Ks[r * 65 + c + 2] = kv.z; Ks[r * 65 + c + 3] = kv.w;
            float4 vv = *(const float4*)(V + base + (size_t)(k0 + r) * D_MODEL + c);
            Vs[r * 65 + c + 0] = vv.x; Vs[r * 65 + c + 1] = vv.y;
            Vs[r * 65 + c + 2] = vv.z; Vs[r * 65 + c + 3] = vv.w;
        }
        __syncthreads();

        float s[4][4];
#pragma unroll
        for (int i = 0; i < 4; i++)
#pragma unroll
            for (int j = 0; j < 4; j++) s[i][j] = 0.f;

#pragma unroll 4
        for (int k = 0; k < 64; k++) {
            float ra[4], rb[4];
#pragma unroll
            for (int i = 0; i < 4; i++) ra[i] = Qs[(ty * 4 + i) * 64 + k];
#pragma unroll
            for (int j = 0; j < 4; j++) rb[j] = Ks[(tx * 4 + j) * 65 + k];
#pragma unroll
            for (int i = 0; i < 4; i++)
#pragma unroll
                for (int j = 0; j < 4; j++) s[i][j] = fmaf(ra[i], rb[j], s[i][j]);
        }
        const bool diag = (kb == qb);
#pragma unroll
        for (int i = 0; i < 4; i++) {
#pragma unroll
            for (int j = 0; j < 4; j++) {
                float v = s[i][j] * 0.125f;
                if (diag && (tx * 4 + j) > (ty * 4 + i)) v = -INFINITY;
                Ss[(ty * 4 + i) * 64 + tx * 4 + j] = v;
            }
        }
        __syncthreads();

        if (tid < 64) {
            const int r = tid;
            float mold = mrow[r];
            float mx = mold;
#pragma unroll 8
            for (int c = 0; c < 64; c++) mx = fmaxf(mx, Ss[r * 64 + c]);
            float corr = __expf(mold - mx);
            float sum = 0.f;
#pragma unroll 8
            for (int c = 0; c < 64; c++) {
                float p = __expf(Ss[r * 64 + c] - mx);
                Ss[r * 64 + c] = p;
                sum += p;
            }
            mrow[r] = mx;
            lrow[r] = lrow[r] * corr + sum;
            crow[r] = corr;
        }
        __syncthreads();

#pragma unroll
        for (int i = 0; i < 4; i++) {
            float c0 = crow[ty * 4 + i];
#pragma unroll
            for (int j = 0; j < 4; j++) accO[i][j] *= c0;
        }
#pragma unroll 4
        for (int k = 0; k < 64; k++) {
            float pv[4], vv[4];
#pragma unroll
            for (int i = 0; i < 4; i++) pv[i] = Ss[(ty * 4 + i) * 64 + k];
#pragma unroll
            for (int j = 0; j < 4; j++) vv[j] = Vs[k * 65 + tx * 4 + j];
#pragma unroll
            for (int i = 0; i < 4; i++)
#pragma unroll
                for (int j = 0; j < 4; j++) accO[i][j] = fmaf(pv[i], vv[j], accO[i][j]);
        }
        __syncthreads();
    }

#pragma unroll
    for (int i = 0; i < 4; i++) {
        const int r = ty * 4 + i;
        const float inv = 1.f / lrow[r];
#pragma unroll
        for (int j = 0; j < 4; j++) {
            O[base + (size_t)(q0 + r) * D_MODEL + tx * 4 + j] = accO[i][j] * inv;
        }
    }
}

// ---------------- LayerNorm (ddof=1, torch-style) ----------------------------
__global__ __launch_bounds__(256)
void layernorm_k(const float* __restrict__ in, const float* __restrict__ gamma,
                 const float* __restrict__ beta, float* __restrict__ out)
{
    const int row = blockIdx.x;
    const int tid = threadIdx.x;
    const float4 v = ((const float4*)(in + (size_t)row * D_MODEL))[tid];
    float s  = v.x + v.y + v.z + v.w;
    float ss = v.x * v.x + v.y * v.y + v.z * v.z + v.w * v.w;

    __shared__ float rs[8], rss[8];
#pragma unroll
    for (int o = 16; o > 0; o >>= 1) {
        s  += __shfl_down_sync(0xFFFFFFFFu, s, o);
        ss += __shfl_down_sync(0xFFFFFFFFu, ss, o);
    }
    if ((tid & 31) == 0) { rs[tid >> 5] = s; rss[tid >> 5] = ss; }
    __syncthreads();
    float S = 0.f, SS = 0.f;
#pragma unroll
    for (int i = 0; i < 8; i++) { S += rs[i]; SS += rss[i]; }

    const float mean = S * (1.f / (float)D_MODEL);
    const float var  = (SS - (float)D_MODEL * mean * mean) * (1.f / (float)(D_MODEL - 1));
    const float inv  = rsqrtf(var + EPS_LN);

    const float4 g = ((const float4*)gamma)[tid];
    const float4 b = ((const float4*)beta)[tid];
    float4 o;
    o.x = g.x * (v.x - mean) * inv + b.x;
    o.y = g.y * (v.y - mean) * inv + b.y;
    o.z = g.z * (v.z - mean) * inv + b.z;
    o.w = g.w * (v.w - mean) * inv + b.w;
    ((float4*)(out + (size_t)row * D_MODEL))[tid] = o;
}

// ---------------- host launcher ---------------------------------------------
extern "C" void kernel_launch(void* const* d_in, const int* in_sizes, int n_in,
                              void* d_out, int out_size)
{
    (void)in_sizes; (void)n_in; (void)out_size;
    const float* x  = (const float*)d_in[0];
    const float* Wq = (const float*)d_in[2];
    const float* Wk = (const float*)d_in[3];
    const float* Wv = (const float*)d_in[4];
    const float* Wo = (const float*)d_in[5];
    const float* W1 = (const float*)d_in[6];
    const float* W2 = (const float*)d_in[7];
    const float* g1 = (const float*)d_in[8];
    const float* b1 = (const float*)d_in[9];
    const float* g2 = (const float*)d_in[10];
    const float* b2 = (const float*)d_in[11];
    float* out = (float*)d_out;

    float *q, *k, *v, *attn, *tmp, *r1, *ff, *tmp2;
    cudaGetSymbolAddress((void**)&q,    g_q);
    cudaGetSymbolAddress((void**)&k,    g_k);
    cudaGetSymbolAddress((void**)&v,    g_v);
    cudaGetSymbolAddress((void**)&attn, g_attn);
    cudaGetSymbolAddress((void**)&tmp,  g_tmp);
    cudaGetSymbolAddress((void**)&r1,   g_r1);
    cudaGetSymbolAddress((void**)&ff,   g_ff);
    cudaGetSymbolAddress((void**)&tmp2, g_tmp2);

    cudaFuncSetAttribute(gemm_wmma<0>, cudaFuncAttributeMaxDynamicSharedMemorySize, GEMM_SMEM);
    cudaFuncSetAttribute(gemm_wmma<1>, cudaFuncAttributeMaxDynamicSharedMemorySize, GEMM_SMEM);
    cudaFuncSetAttribute(gemm_wmma<2>, cudaFuncAttributeMaxDynamicSharedMemorySize, GEMM_SMEM);

    const dim3 blk(256);
    const dim3 gD(D_MODEL / 128, MROWS / 128);   // (8, 32)
    const dim3 gF(D_FF / 128, MROWS / 128);      // (32, 32)

    // QKV projections
    gemm_wmma<0><<<gD, blk, GEMM_SMEM>>>(x, Wq, nullptr, q, MROWS, D_MODEL, D_MODEL);
    gemm_wmma<0><<<gD, blk, GEMM_SMEM>>>(x, Wk, nullptr, k, MROWS, D_MODEL, D_MODEL);
    gemm_wmma<0><<<gD, blk, GEMM_SMEM>>>(x, Wv, nullptr, v, MROWS, D_MODEL, D_MODEL);

    // Flash attention
    const int smem = (64 * 64 + 2 * 64 * 65 + 64 * 64 + 3 * 64) * (int)sizeof(float); // 66816 B
    cudaFuncSetAttribute(flash_attn, cudaFuncAttributeMaxDynamicSharedMemorySize, smem);
    flash_attn<<<dim3(SEQ / 64, HEADS, BATCH), blk, smem>>>(q, k, v, attn);

    // Output projection + residual, then LN1
    gemm_wmma<2><<<gD, blk, GEMM_SMEM>>>(attn, Wo, x, tmp, MROWS, D_MODEL, D_MODEL);
    layernorm_k<<<MROWS, blk>>>(tmp, g1, b1, r1);

    // FFN
    gemm_wmma<1><<<gF, blk, GEMM_SMEM>>>(r1, W1, nullptr, ff, MROWS, D_FF, D_MODEL);
    gemm_wmma<2><<<gD, blk, GEMM_SMEM>>>(ff, W2, r1, tmp2, MROWS, D_MODEL, D_FF);
    layernorm_k<<<MROWS, blk>>>(tmp2, g2, b2, out);
}

// round 4
// speedup vs baseline: 1.9176x; 1.1944x over previous
#include <cuda_runtime.h>
#include <cuda_bf16.h>
#include <mma.h>
#include <math.h>
#include <stdint.h>

using namespace nvcuda;

#define D_MODEL 1024
#define HEADS   16
#define DKH     64
#define D_FF    4096
#define BATCH   2
#define SEQ     2048
#define MROWS   (BATCH * SEQ)   // 4096
#define EPS_LN  1e-6f

// ---------------- scratch (static device globals; no allocs) ----------------
__device__ float g_q[MROWS * D_MODEL];
__device__ float g_k[MROWS * D_MODEL];
__device__ float g_v[MROWS * D_MODEL];
__device__ float g_attn[MROWS * D_MODEL];
__device__ float g_tmp[MROWS * D_MODEL];
__device__ float g_r1[MROWS * D_MODEL];
__device__ float g_ff[MROWS * D_FF];
__device__ float g_tmp2[MROWS * D_MODEL];

// ================= bf16 split helpers =======================================
__device__ __forceinline__ void split2(float a, float b, uint32_t& hi, uint32_t& lo) {
    __nv_bfloat16 ha = __float2bfloat16_rn(a);
    __nv_bfloat16 hb = __float2bfloat16_rn(b);
    float la = a - __bfloat162float(ha);
    float lb = b - __bfloat162float(hb);
    __nv_bfloat162 hv = __halves2bfloat162(ha, hb);
    __nv_bfloat162 lv = __floats2bfloat162_rn(la, lb);
    hi = *reinterpret_cast<uint32_t*>(&hv);
    lo = *reinterpret_cast<uint32_t*>(&lv);
}

// ================= WMMA GEMM: C = A @ B^T (+epilogue), bf16x3 ================
#define WBK   32
#define LDT   40
#define TILE_E (128 * LDT)
#define STAGE_E (4 * TILE_E)
#define GEMM_SMEM (2 * STAGE_E * (int)sizeof(__nv_bfloat16))   // 81920 B

__device__ __forceinline__ void cvt_store(__nv_bfloat16* hi, __nv_bfloat16* lo,
                                          int r, int c4, float4 v) {
    uint32_t h01, l01, h23, l23;
    split2(v.x, v.y, h01, l01);
    split2(v.z, v.w, h23, l23);
    *(uint2*)(hi + r * LDT + c4) = make_uint2(h01, h23);
    *(uint2*)(lo + r * LDT + c4) = make_uint2(l01, l23);
}

template <int EPI>
__global__ __launch_bounds__(256)
void gemm_wmma(const float* __restrict__ A, const float* __restrict__ B,
               const float* __restrict__ R, float* __restrict__ C,
               int M, int N, int K)
{
    extern __shared__ __nv_bfloat16 sh[];

    const int tid = threadIdx.x;
    const int wid = tid >> 5;
    const int wm = (wid & 3) * 32;
    const int wn = (wid >> 2) * 64;

    const int row0 = blockIdx.y * 128;
    const int col0 = blockIdx.x * 128;
    const float* Ab = A + (size_t)row0 * K;
    const float* Bb = B + (size_t)col0 * K;

    wmma::fragment<wmma::accumulator, 16, 16, 16, float> acc[2][4];
#pragma unroll
    for (int i = 0; i < 2; i++)
#pragma unroll
        for (int j = 0; j < 4; j++) wmma::fill_fragment(acc[i][j], 0.f);

    const int lr = tid >> 3;
    const int lc4 = (tid & 7) << 2;

    float4 ar[4], br[4];
#pragma unroll
    for (int it = 0; it < 4; it++) {
        int r = lr + it * 32;
        ar[it] = *(const float4*)(Ab + (size_t)r * K + lc4);
        br[it] = *(const float4*)(Bb + (size_t)r * K + lc4);
    }
    {
        __nv_bfloat16* Ah = sh;
        __nv_bfloat16* Al = Ah + TILE_E;
        __nv_bfloat16* Bh = Al + TILE_E;
        __nv_bfloat16* Bl = Bh + TILE_E;
#pragma unroll
        for (int it = 0; it < 4; it++) {
            int r = lr + it * 32;
            cvt_store(Ah, Al, r, lc4, ar[it]);
            cvt_store(Bh, Bl, r, lc4, br[it]);
        }
    }
    __syncthreads();

    const int T = K / WBK;
    for (int t = 0; t < T; t++) {
        const int cur = t & 1;
        const int nxt = cur ^ 1;

        if (t + 1 < T) {
            const int k0 = (t + 1) * WBK;
#pragma unroll
            for (int it = 0; it < 4; it++) {
                int r = lr + it * 32;
                ar[it] = *(const float4*)(Ab + (size_t)r * K + k0 + lc4);
                br[it] = *(const float4*)(Bb + (size_t)r * K + k0 + lc4);
            }
        }

        {
            __nv_bfloat16* Ah = sh + cur * STAGE_E;
            __nv_bfloat16* Al = Ah + TILE_E;
            __nv_bfloat16* Bh = Al + TILE_E;
            __nv_bfloat16* Bl = Bh + TILE_E;
#pragma unroll
            for (int ks = 0; ks < WBK; ks += 16) {
                wmma::fragment<wmma::matrix_a, 16, 16, 16, __nv_bfloat16, wmma::row_major> a_hi[2], a_lo[2];
                wmma::fragment<wmma::matrix_b, 16, 16, 16, __nv_bfloat16, wmma::col_major> b_hi[4], b_lo[4];
#pragma unroll
                for (int i = 0; i < 2; i++) {
                    wmma::load_matrix_sync(a_hi[i], Ah + (wm + i * 16) * LDT + ks, LDT);
                    wmma::load_matrix_sync(a_lo[i], Al + (wm + i * 16) * LDT + ks, LDT);
                }
#pragma unroll
                for (int j = 0; j < 4; j++) {
                    wmma::load_matrix_sync(b_hi[j], Bh + (wn + j * 16) * LDT + ks, LDT);
                    wmma::load_matrix_sync(b_lo[j], Bl + (wn + j * 16) * LDT + ks, LDT);
                }
#pragma unroll
                for (int i = 0; i < 2; i++) {
#pragma unroll
                    for (int j = 0; j < 4; j++) {
                        wmma::mma_sync(acc[i][j], a_hi[i], b_hi[j], acc[i][j]);
                        wmma::mma_sync(acc[i][j], a_hi[i], b_lo[j], acc[i][j]);
                        wmma::mma_sync(acc[i][j], a_lo[i], b_hi[j], acc[i][j]);
                    }
                }
            }
        }

        if (t + 1 < T) {
            __nv_bfloat16* Ah = sh + nxt * STAGE_E;
            __nv_bfloat16* Al = Ah + TILE_E;
            __nv_bfloat16* Bh = Al + TILE_E;
            __nv_bfloat16* Bl = Bh + TILE_E;
#pragma unroll
            for (int it = 0; it < 4; it++) {
                int r = lr + it * 32;
                cvt_store(Ah, Al, r, lc4, ar[it]);
                cvt_store(Bh, Bl, r, lc4, br[it]);
            }
        }
        __syncthreads();
    }

#pragma unroll
    for (int i = 0; i < 2; i++) {
#pragma unroll
        for (int j = 0; j < 4; j++) {
            const int row = row0 + wm + i * 16;
            const int col = col0 + wn + j * 16;
            float* cptr = C + (size_t)row * N + col;
            if (EPI == 2) {
                wmma::fragment<wmma::accumulator, 16, 16, 16, float> rf;
                wmma::load_matrix_sync(rf, R + (size_t)row * N + col, N, wmma::mem_row_major);
#pragma unroll
                for (int e = 0; e < rf.num_elements; e++) acc[i][j].x[e] += rf.x[e];
            }
            if (EPI == 1) {
#pragma unroll
                for (int e = 0; e < acc[i][j].num_elements; e++)
                    acc[i][j].x[e] = fmaxf(acc[i][j].x[e], 0.f);
            }
            wmma::store_matrix_sync(cptr, acc[i][j], N, wmma::mem_row_major);
        }
    }
}

// ================= WMMA flash attention (bf16x3, fp32 softmax) ===============
// grid: (SEQ/64, HEADS, BATCH), 256 threads = 8 warps (2m x 4n), tile 64x64.
#define LDH 72          // bf16 row stride
#define LDF 68          // fp32 row stride
// smem byte offsets
#define FO_QH 0
#define FO_QL (FO_QH + 64 * LDH * 2)      // 9216 each
#define FO_KH (FO_QL + 64 * LDH * 2)
#define FO_KL (FO_KH + 64 * LDH * 2)
#define FO_VH (FO_KL + 64 * LDH * 2)
#define FO_VL (FO_VH + 64 * LDH * 2)
#define FO_PH (FO_VL + 64 * LDH * 2)
#define FO_PL (FO_PH + 64 * LDH * 2)
#define FO_SF (FO_PL + 64 * LDH * 2)      // fp32 64*68
#define FO_OF (FO_SF + 64 * LDF * 4)
#define FO_MR (FO_OF + 64 * LDF * 4)
#define FO_LR (FO_MR + 256)
#define FO_CR (FO_LR + 256)
#define FA_SMEM (FO_CR + 256)             // 109312 B

__device__ __forceinline__ void cvt_f4(__nv_bfloat16* hi, __nv_bfloat16* lo,
                                       int r, int c, float4 v) {
    uint32_t h01, l01, h23, l23;
    split2(v.x, v.y, h01, l01);
    split2(v.z, v.w, h23, l23);
    *(uint2*)(hi + r * LDH + c) = make_uint2(h01, h23);
    *(uint2*)(lo + r * LDH + c) = make_uint2(l01, l23);
}

__global__ __launch_bounds__(256, 1)
void flash_wmma(const float* __restrict__ Q, const float* __restrict__ Kg,
                const float* __restrict__ V, float* __restrict__ O)
{
    extern __shared__ char fsm[];
    __nv_bfloat16* Qh = (__nv_bfloat16*)(fsm + FO_QH);
    __nv_bfloat16* Ql = (__nv_bfloat16*)(fsm + FO_QL);
    __nv_bfloat16* Kh = (__nv_bfloat16*)(fsm + FO_KH);
    __nv_bfloat16* Kl = (__nv_bfloat16*)(fsm + FO_KL);
    __nv_bfloat16* Vh = (__nv_bfloat16*)(fsm + FO_VH);
    __nv_bfloat16* Vl = (__nv_bfloat16*)(fsm + FO_VL);
    __nv_bfloat16* Ph = (__nv_bfloat16*)(fsm + FO_PH);
    __nv_bfloat16* Pl = (__nv_bfloat16*)(fsm + FO_PL);
    float* Sf   = (float*)(fsm + FO_SF);
    float* Of   = (float*)(fsm + FO_OF);
    float* mrow = (float*)(fsm + FO_MR);
    float* lrow = (float*)(fsm + FO_LR);
    float* crow = (float*)(fsm + FO_CR);

    const int qb = blockIdx.x, h = blockIdx.y, bb = blockIdx.z;
    const int tid = threadIdx.x;
    const int wid = tid >> 5;
    const int wm = (wid & 1) * 32;        // warp m offset (2)
    const int wn = (wid >> 1) * 16;       // warp n offset (4)
    const int q0 = qb * 64;
    const size_t base = (size_t)bb * SEQ * D_MODEL + (size_t)h * DKH;

    // per-thread row mapping for loads/softmax: 4 threads per row
    const int r  = tid >> 2;              // 0..63
    const int qq = tid & 3;               // 0..3
    const int c0 = qq * 16;

    // ---- load + convert Q block; init state ----
#pragma unroll
    for (int j = 0; j < 16; j += 4) {
        float4 v = *(const float4*)(Q + base + (size_t)(q0 + r) * D_MODEL + c0 + j);
        cvt_f4(Qh, Ql, r, c0 + j, v);
    }
#pragma unroll
    for (int i = 0; i < 17; i++) Of[tid + i * 256] = 0.f;   // 64*68 = 4352 = 17*256
    if (tid < 64) { mrow[tid] = -INFINITY; lrow[tid] = 0.f; }
    __syncthreads();

    for (int kb = 0; kb <= qb; kb++) {
        const int k0 = kb * 64;

        // ---- 1. load + convert K, V ----
#pragma unroll
        for (int j = 0; j < 16; j += 4) {
            float4 kv = *(const float4*)(Kg + base + (size_t)(k0 + r) * D_MODEL + c0 + j);
            cvt_f4(Kh, Kl, r, c0 + j, kv);
            float4 vv = *(const float4*)(V + base + (size_t)(k0 + r) * D_MODEL + c0 + j);
            cvt_f4(Vh, Vl, r, c0 + j, vv);
        }
        __syncthreads();

        // ---- 2. S = Q K^T (bf16x3) ----
        {
            wmma::fragment<wmma::accumulator, 16, 16, 16, float> accS[2];
#pragma unroll
            for (int i = 0; i < 2; i++) wmma::fill_fragment(accS[i], 0.f);
#pragma unroll
            for (int ks = 0; ks < 64; ks += 16) {
                wmma::fragment<wmma::matrix_a, 16, 16, 16, __nv_bfloat16, wmma::row_major> ah[2], al[2];
                wmma::fragment<wmma::matrix_b, 16, 16, 16, __nv_bfloat16, wmma::col_major> bh, bl;
#pragma unroll
                for (int i = 0; i < 2; i++) {
                    wmma::load_matrix_sync(ah[i], Qh + (wm + i * 16) * LDH + ks, LDH);
                    wmma::load_matrix_sync(al[i], Ql + (wm + i * 16) * LDH + ks, LDH);
                }
                wmma::load_matrix_sync(bh, Kh + wn * LDH + ks, LDH);
                wmma::load_matrix_sync(bl, Kl + wn * LDH + ks, LDH);
#pragma unroll
                for (int i = 0; i < 2; i++) {
                    wmma::mma_sync(accS[i], ah[i], bh, accS[i]);
                    wmma::mma_sync(accS[i], ah[i], bl, accS[i]);
                    wmma::mma_sync(accS[i], al[i], bh, accS[i]);
                }
            }
#pragma unroll
            for (int i = 0; i < 2; i++)
                wmma::store_matrix_sync(Sf + (wm + i * 16) * LDF + wn, accS[i], LDF, wmma::mem_row_major);
        }
        __syncthreads();

        // ---- 3. softmax (4 threads per row) + P conversion ----
        {
            const bool diag = (kb == qb);
            const int qrow = q0 + r;
            float sv[16];
            const float* srow = Sf + r * LDF + c0;
            float mx = -INFINITY;
#pragma unroll
            for (int j = 0; j < 16; j++) {
                float v = srow[j] * 0.125f;
                if (diag && (k0 + c0 + j) > qrow) v = -INFINITY;
                sv[j] = v;
                mx = fmaxf(mx, v);
            }
            mx = fmaxf(mx, __shfl_xor_sync(0xFFFFFFFFu, mx, 1));
            mx = fmaxf(mx, __shfl_xor_sync(0xFFFFFFFFu, mx, 2));
            const float mold = mrow[r];
            const float mnew = fmaxf(mold, mx);
            float lsum = 0.f;
#pragma unroll
            for (int j = 0; j < 16; j++) {
                float p = __expf(sv[j] - mnew);
                sv[j] = p;
                lsum += p;
            }
            lsum += __shfl_xor_sync(0xFFFFFFFFu, lsum, 1);
            lsum += __shfl_xor_sync(0xFFFFFFFFu, lsum, 2);
            // store P hi/lo
#pragma unroll
            for (int j = 0; j < 16; j += 2) {
                uint32_t hv, lv;
                split2(sv[j], sv[j + 1], hv, lv);
                *(uint32_t*)(Ph + r * LDH + c0 + j) = hv;
                *(uint32_t*)(Pl + r * LDH + c0 + j) = lv;
            }
            if (qq == 0) {
                const float corr = __expf(mold - mnew);
                mrow[r] = mnew;
                lrow[r] = lrow[r] * corr + lsum;
                crow[r] = corr;
            }
        }
        __syncthreads();

        // ---- 4. PV = P @ V (bf16x3) -> stage into Sf ----
        {
            wmma::fragment<wmma::accumulator, 16, 16, 16, float> accO[2];
#pragma unroll
            for (int i = 0; i < 2; i++) wmma::fill_fragment(accO[i], 0.f);
#pragma unroll
            for (int ks = 0; ks < 64; ks += 16) {
                wmma::fragment<wmma::matrix_a, 16, 16, 16, __nv_bfloat16, wmma::row_major> ah[2], al[2];
                wmma::fragment<wmma::matrix_b, 16, 16, 16, __nv_bfloat16, wmma::row_major> bh, bl;
#pragma unroll
                for (int i = 0; i < 2; i++) {
                    wmma::load_matrix_sync(ah[i], Ph + (wm + i * 16) * LDH + ks, LDH);
                    wmma::load_matrix_sync(al[i], Pl + (wm + i * 16) * LDH + ks, LDH);
                }
                wmma::load_matrix_sync(bh, Vh + ks * LDH + wn, LDH);
                wmma::load_matrix_sync(bl, Vl + ks * LDH + wn, LDH);
#pragma unroll
                for (int i = 0; i < 2; i++) {
                    wmma::mma_sync(accO[i], ah[i], bh, accO[i]);
                    wmma::mma_sync(accO[i], ah[i], bl, accO[i]);
                    wmma::mma_sync(accO[i], al[i], bh, accO[i]);
                }
            }
#pragma unroll
            for (int i = 0; i < 2; i++)
                wmma::store_matrix_sync(Sf + (wm + i * 16) * LDF + wn, accO[i], LDF, wmma::mem_row_major);
        }
        __syncthreads();

        // ---- 5. O = O*corr + PV ----
        {
            const float corr = crow[r];
            float* orow = Of + r * LDF + c0;
            const float* prow = Sf + r * LDF + c0;
#pragma unroll
            for (int j = 0; j < 16; j++) orow[j] = orow[j] * corr + prow[j];
        }
        // no sync needed here: next iteration's first sync gates reuse
        __syncthreads();
    }

    // ---- final normalize + store ----
    {
        const float inv = 1.f / lrow[r];
        const float* orow = Of + r * LDF + c0;
        float* dst = O + base + (size_t)(q0 + r) * D_MODEL + c0;
#pragma unroll
        for (int j = 0; j < 16; j += 4) {
            float4 v;
            v.x = orow[j + 0] * inv;
            v.y = orow[j + 1] * inv;
            v.z = orow[j + 2] * inv;
            v.w = orow[j + 3] * inv;
            *(float4*)(dst + j) = v;
        }
    }
}

// ---------------- LayerNorm (ddof=1, torch-style) ----------------------------
__global__ __launch_bounds__(256)
void layernorm_k(const float* __restrict__ in, const float* __restrict__ gamma,
                 const float* __restrict__ beta, float* __restrict__ out)
{
    const int row = blockIdx.x;
    const int tid = threadIdx.x;
    const float4 v = ((const float4*)(in + (size_t)row * D_MODEL))[tid];
    float s  = v.x + v.y + v.z + v.w;
    float ss = v.x * v.x + v.y * v.y + v.z * v.z + v.w * v.w;

    __shared__ float rs[8], rss[8];
#pragma unroll
    for (int o = 16; o > 0; o >>= 1) {
        s  += __shfl_down_sync(0xFFFFFFFFu, s, o);
        ss += __shfl_down_sync(0xFFFFFFFFu, ss, o);
    }
    if ((tid & 31) == 0) { rs[tid >> 5] = s; rss[tid >> 5] = ss; }
    __syncthreads();
    float S = 0.f, SS = 0.f;
#pragma unroll
    for (int i = 0; i < 8; i++) { S += rs[i]; SS += rss[i]; }

    const float mean = S * (1.f / (float)D_MODEL);
    const float var  = (SS - (float)D_MODEL * mean * mean) * (1.f / (float)(D_MODEL - 1));
    const float inv  = rsqrtf(var + EPS_LN);

    const float4 g = ((const float4*)gamma)[tid];
    const float4 b = ((const float4*)beta)[tid];
    float4 o;
    o.x = g.x * (v.x - mean) * inv + b.x;
    o.y = g.y * (v.y - mean) * inv + b.y;
    o.z = g.z * (v.z - mean) * inv + b.z;
    o.w = g.w * (v.w - mean) * inv + b.w;
    ((float4*)(out + (size_t)row * D_MODEL))[tid] = o;
}

// ---------------- host launcher ---------------------------------------------
extern "C" void kernel_launch(void* const* d_in, const int* in_sizes, int n_in,
                              void* d_out, int out_size)
{
    (void)in_sizes; (void)n_in; (void)out_size;
    const float* x  = (const float*)d_in[0];
    const float* Wq = (const float*)d_in[2];
    const float* Wk = (const float*)d_in[3];
    const float* Wv = (const float*)d_in[4];
    const float* Wo = (const float*)d_in[5];
    const float* W1 = (const float*)d_in[6];
    const float* W2 = (const float*)d_in[7];
    const float* g1 = (const float*)d_in[8];
    const float* b1 = (const float*)d_in[9];
    const float* g2 = (const float*)d_in[10];
    const float* b2 = (const float*)d_in[11];
    float* out = (float*)d_out;

    float *q, *k, *v, *attn, *tmp, *r1, *ff, *tmp2;
    cudaGetSymbolAddress((void**)&q,    g_q);
    cudaGetSymbolAddress((void**)&k,    g_k);
    cudaGetSymbolAddress((void**)&v,    g_v);
    cudaGetSymbolAddress((void**)&attn, g_attn);
    cudaGetSymbolAddress((void**)&tmp,  g_tmp);
    cudaGetSymbolAddress((void**)&r1,   g_r1);
    cudaGetSymbolAddress((void**)&ff,   g_ff);
    cudaGetSymbolAddress((void**)&tmp2, g_tmp2);

    cudaFuncSetAttribute(gemm_wmma<0>, cudaFuncAttributeMaxDynamicSharedMemorySize, GEMM_SMEM);
    cudaFuncSetAttribute(gemm_wmma<1>, cudaFuncAttributeMaxDynamicSharedMemorySize, GEMM_SMEM);
    cudaFuncSetAttribute(gemm_wmma<2>, cudaFuncAttributeMaxDynamicSharedMemorySize, GEMM_SMEM);
    cudaFuncSetAttribute(flash_wmma, cudaFuncAttributeMaxDynamicSharedMemorySize, FA_SMEM);

    const dim3 blk(256);
    const dim3 gD(D_MODEL / 128, MROWS / 128);   // (8, 32)
    const dim3 gF(D_FF / 128, MROWS / 128);      // (32, 32)

    // QKV projections
    gemm_wmma<0><<<gD, blk, GEMM_SMEM>>>(x, Wq, nullptr, q, MROWS, D_MODEL, D_MODEL);
    gemm_wmma<0><<<gD, blk, GEMM_SMEM>>>(x, Wk, nullptr, k, MROWS, D_MODEL, D_MODEL);
    gemm_wmma<0><<<gD, blk, GEMM_SMEM>>>(x, Wv, nullptr, v, MROWS, D_MODEL, D_MODEL);

    // Flash attention (tensor-core)
    flash_wmma<<<dim3(SEQ / 64, HEADS, BATCH), blk, FA_SMEM>>>(q, k, v, attn);

    // Output projection + residual, then LN1
    gemm_wmma<2><<<gD, blk, GEMM_SMEM>>>(attn, Wo, x, tmp, MROWS, D_MODEL, D_MODEL);
    layernorm_k<<<MROWS, blk>>>(tmp, g1, b1, r1);

    // FFN
    gemm_wmma<1><<<gF, blk, GEMM_SMEM>>>(r1, W1, nullptr, ff, MROWS, D_FF, D_MODEL);
    gemm_wmma<2><<<gD, blk, GEMM_SMEM>>>(ff, W2, r1, tmp2, MROWS, D_MODEL, D_FF);
    layernorm_k<<<MROWS, blk>>>(tmp2, g2, b2, out);
}

// round 6
// speedup vs baseline: 2.0955x; 1.0928x over previous
#include <cuda_runtime.h>
#include <cuda_bf16.h>
#include <mma.h>
#include <math.h>
#include <stdint.h>

using namespace nvcuda;

#define D_MODEL 1024
#define HEADS   16
#define DKH     64
#define D_FF    4096
#define BATCH   2
#define SEQ     2048
#define MROWS   (BATCH * SEQ)   // 4096
#define EPS_LN  1e-6f
#define NELEM   (MROWS * D_MODEL)    // 4194304
#define WELEM   (D_MODEL * D_MODEL)  // 1048576
#define FELEM   (D_FF * D_MODEL)     // 4194304
#define FFELEM  (MROWS * D_FF)       // 16777216

// ---------------- scratch (static device globals; no allocs) ----------------
__device__ __nv_bfloat16 g_xh[NELEM],  g_xl[NELEM];
__device__ __nv_bfloat16 g_wqh[WELEM], g_wql[WELEM];
__device__ __nv_bfloat16 g_wkh[WELEM], g_wkl[WELEM];
__device__ __nv_bfloat16 g_wvh[WELEM], g_wvl[WELEM];
__device__ __nv_bfloat16 g_woh[WELEM], g_wol[WELEM];
__device__ __nv_bfloat16 g_w1h[FELEM], g_w1l[FELEM];
__device__ __nv_bfloat16 g_w2h[FELEM], g_w2l[FELEM];
__device__ __nv_bfloat16 g_qh[NELEM],  g_ql[NELEM];
__device__ __nv_bfloat16 g_kh[NELEM],  g_kl[NELEM];
__device__ __nv_bfloat16 g_vh[NELEM],  g_vl[NELEM];
__device__ __nv_bfloat16 g_ah[NELEM],  g_al[NELEM];
__device__ __nv_bfloat16 g_r1h[NELEM], g_r1l[NELEM];
__device__ __nv_bfloat16 g_ffh[FFELEM], g_ffl[FFELEM];
__device__ float g_tmp[NELEM];
__device__ float g_r1f[NELEM];
__device__ float g_tmp2[NELEM];

// ================= helpers ===================================================
__device__ __forceinline__ void split2(float a, float b, uint32_t& hi, uint32_t& lo) {
    __nv_bfloat16 ha = __float2bfloat16_rn(a);
    __nv_bfloat16 hb = __float2bfloat16_rn(b);
    float la = a - __bfloat162float(ha);
    float lb = b - __bfloat162float(hb);
    __nv_bfloat162 hv = __halves2bfloat162(ha, hb);
    __nv_bfloat162 lv = __floats2bfloat162_rn(la, lb);
    hi = *reinterpret_cast<uint32_t*>(&hv);
    lo = *reinterpret_cast<uint32_t*>(&lv);
}

#define CP16(dst, src) \
    asm volatile("cp.async.cg.shared.global [%0], [%1], 16;" :: \
        "r"((uint32_t)__cvta_generic_to_shared(dst)), "l"(src))
#define CP_COMMIT() asm volatile("cp.async.commit_group;" ::: "memory")
#define CP_WAIT(n)  asm volatile("cp.async.wait_group %0;" :: "n"(n) : "memory")

// ---------------- fp32 -> bf16 hi/lo conversion ------------------------------
__global__ __launch_bounds__(256)
void cvt_hl(const float* __restrict__ src, __nv_bfloat16* __restrict__ hi,
            __nv_bfloat16* __restrict__ lo, int n4)
{
    int i = blockIdx.x * 256 + threadIdx.x;
    if (i < n4) {
        float4 v = ((const float4*)src)[i];
        uint32_t h01, l01, h23, l23;
        split2(v.x, v.y, h01, l01);
        split2(v.z, v.w, h23, l23);
        ((uint2*)hi)[i] = make_uint2(h01, h23);
        ((uint2*)lo)[i] = make_uint2(l01, l23);
    }
}

// ================= WMMA GEMM: C = A @ B^T (+epilogue), bf16x3 ================
// pre-split bf16 inputs: Ah/Al [M,K] rm, Bh/Bl [N,K] rm.
// EPI: 0 none, 1 relu, 2 residual (+Rf). OUT: 0 fp32 Cf, 1 bf16 hi/lo Ch/Cl.
#define GLDT    40                          // smem row stride (bf16)
#define GTILE   (128 * GLDT)                // 5120 elems / tile
#define GSTAGE  (4 * GTILE)                 // Ah,Al,Bh,Bl
#define GSTAGES 3
#define GEMM_SMEM (GSTAGES * GSTAGE * 2)    // 122880 B

__device__ __forceinline__ void gemm_issue(__nv_bfloat16* st,
    const __nv_bfloat16* Ahg, const __nv_bfloat16* Alg,
    const __nv_bfloat16* Bhg, const __nv_bfloat16* Blg,
    int K, int k0, int tid)
{
    const __nv_bfloat16* srcs[4] = {Ahg, Alg, Bhg, Blg};
#pragma unroll
    for (int tile = 0; tile < 4; tile++) {
        __nv_bfloat16* dst = st + tile * GTILE;
        const __nv_bfloat16* g = srcs[tile];
#pragma unroll
        for (int it = 0; it < 2; it++) {
            int ch = tid + it * 256;         // 0..511
            int r = ch >> 2;
            int c = (ch & 3) * 8;            // bf16 elems (16B chunks)
            CP16(dst + r * GLDT + c, g + (size_t)r * K + k0 + c);
        }
    }
}

template <int EPI, int OUT>
__global__ __launch_bounds__(256)
void gemm_bf(const __nv_bfloat16* __restrict__ Ah, const __nv_bfloat16* __restrict__ Al,
             const __nv_bfloat16* __restrict__ Bh, const __nv_bfloat16* __restrict__ Bl,
             const float* __restrict__ Rf, float* __restrict__ Cf,
             __nv_bfloat16* __restrict__ Ch, __nv_bfloat16* __restrict__ Cl,
             int M, int N, int K)
{
    extern __shared__ __nv_bfloat16 sh[];

    const int tid = threadIdx.x;
    const int wid = tid >> 5;
    const int wm = (wid & 3) * 32;
    const int wn = (wid >> 2) * 64;

    const int row0 = blockIdx.y * 128;
    const int col0 = blockIdx.x * 128;
    const __nv_bfloat16* Ahg = Ah + (size_t)row0 * K;
    const __nv_bfloat16* Alg = Al + (size_t)row0 * K;
    const __nv_bfloat16* Bhg = Bh + (size_t)col0 * K;
    const __nv_bfloat16* Blg = Bl + (size_t)col0 * K;

    wmma::fragment<wmma::accumulator, 16, 16, 16, float> acc[2][4];
#pragma unroll
    for (int i = 0; i < 2; i++)
#pragma unroll
        for (int j = 0; j < 4; j++) wmma::fill_fragment(acc[i][j], 0.f);

    const int T = K / 32;
    gemm_issue(sh, Ahg, Alg, Bhg, Blg, K, 0, tid);
    CP_COMMIT();
    gemm_issue(sh + GSTAGE, Ahg, Alg, Bhg, Blg, K, 32, tid);
    CP_COMMIT();

    for (int t = 0; t < T; t++) {
        if (t + 1 < T) { CP_WAIT(1); } else { CP_WAIT(0); }
        __syncthreads();
        if (t + 2 < T) {
            gemm_issue(sh + ((t + 2) % GSTAGES) * GSTAGE, Ahg, Alg, Bhg, Blg,
                       K, (t + 2) * 32, tid);
            CP_COMMIT();
        }
        __nv_bfloat16* Ahs = sh + (t % GSTAGES) * GSTAGE;
        __nv_bfloat16* Als = Ahs + GTILE;
        __nv_bfloat16* Bhs = Ahs + 2 * GTILE;
        __nv_bfloat16* Bls = Ahs + 3 * GTILE;
#pragma unroll
        for (int ks = 0; ks < 32; ks += 16) {
            wmma::fragment<wmma::matrix_a, 16, 16, 16, __nv_bfloat16, wmma::row_major> a_hi[2], a_lo[2];
            wmma::fragment<wmma::matrix_b, 16, 16, 16, __nv_bfloat16, wmma::col_major> b_hi[4], b_lo[4];
#pragma unroll
            for (int i = 0; i < 2; i++) {
                wmma::load_matrix_sync(a_hi[i], Ahs + (wm + i * 16) * GLDT + ks, GLDT);
                wmma::load_matrix_sync(a_lo[i], Als + (wm + i * 16) * GLDT + ks, GLDT);
            }
#pragma unroll
            for (int j = 0; j < 4; j++) {
                wmma::load_matrix_sync(b_hi[j], Bhs + (wn + j * 16) * GLDT + ks, GLDT);
                wmma::load_matrix_sync(b_lo[j], Bls + (wn + j * 16) * GLDT + ks, GLDT);
            }
#pragma unroll
            for (int i = 0; i < 2; i++) {
#pragma unroll
                for (int j = 0; j < 4; j++) {
                    wmma::mma_sync(acc[i][j], a_hi[i], b_hi[j], acc[i][j]);
                    wmma::mma_sync(acc[i][j], a_hi[i], b_lo[j], acc[i][j]);
                    wmma::mma_sync(acc[i][j], a_lo[i], b_hi[j], acc[i][j]);
                }
            }
        }
    }

    if (OUT == 0) {
        // fp32 out (+optional residual)
#pragma unroll
        for (int i = 0; i < 2; i++) {
#pragma unroll
            for (int j = 0; j < 4; j++) {
                const int row = row0 + wm + i * 16;
                const int col = col0 + wn + j * 16;
                if (EPI == 2) {
                    wmma::fragment<wmma::accumulator, 16, 16, 16, float> rf;
                    wmma::load_matrix_sync(rf, Rf + (size_t)row * N + col, N, wmma::mem_row_major);
#pragma unroll
                    for (int e = 0; e < rf.num_elements; e++) acc[i][j].x[e] += rf.x[e];
                }
                if (EPI == 1) {
#pragma unroll
                    for (int e = 0; e < acc[i][j].num_elements; e++)
                        acc[i][j].x[e] = fmaxf(acc[i][j].x[e], 0.f);
                }
                wmma::store_matrix_sync(Cf + (size_t)row * N + col, acc[i][j], N, wmma::mem_row_major);
            }
        }
    } else {
        // bf16 hi/lo out: stage fp32 tile in smem, then split-store
        float* stg = (float*)sh;             // 128 x 132 fp32, reuses stage smem
        __syncthreads();
#pragma unroll
        for (int i = 0; i < 2; i++) {
#pragma unroll
            for (int j = 0; j < 4; j++) {
                if (EPI == 1) {
#pragma unroll
                    for (int e = 0; e < acc[i][j].num_elements; e++)
                        acc[i][j].x[e] = fmaxf(acc[i][j].x[e], 0.f);
                }
                wmma::store_matrix_sync(stg + (wm + i * 16) * 132 + wn + j * 16,
                                        acc[i][j], 132, wmma::mem_row_major);
            }
        }
        __syncthreads();
        const int r = tid >> 1;
        const int cb = (tid & 1) * 64;
#pragma unroll
        for (int j = 0; j < 64; j += 4) {
            float4 v = *(const float4*)(stg + r * 132 + cb + j);
            uint32_t h01, l01, h23, l23;
            split2(v.x, v.y, h01, l01);
            split2(v.z, v.w, h23, l23);
            const size_t off = (size_t)(row0 + r) * N + col0 + cb + j;
            *(uint2*)(Ch + off) = make_uint2(h01, h23);
            *(uint2*)(Cl + off) = make_uint2(l01, l23);
        }
    }
}

// ================= WMMA flash attention (bf16x3 in/out, fp32 softmax) ========
// grid: (SEQ/128, HEADS, BATCH), 512 threads = 16 warps (4m x 4n).
// Q tile 128, K tile 64. O accumulator in registers (16 f32/thread).
#define LDH 72
#define LDF 68
#define FO_QH 0
#define FO_QL (FO_QH + 128 * LDH * 2)     // 18432 each
#define FO_KH (FO_QL + 128 * LDH * 2)
#define FO_KL (FO_KH + 64 * LDH * 2)      // 9216 each
#define FO_VH (FO_KL + 64 * LDH * 2)
#define FO_VL (FO_VH + 64 * LDH * 2)
#define FO_PH (FO_VL + 64 * LDH * 2)
#define FO_PL (FO_PH + 128 * LDH * 2)
#define FO_SF (FO_PL + 128 * LDH * 2)     // fp32 128*68
#define FO_MR (FO_SF + 128 * LDF * 4)
#define FO_LR (FO_MR + 512)
#define FO_CR (FO_LR + 512)
#define FA_SMEM (FO_CR + 512)             // 146944 B

__global__ __launch_bounds__(512)
void flash_bf(const __nv_bfloat16* __restrict__ Qh_g, const __nv_bfloat16* __restrict__ Ql_g,
              const __nv_bfloat16* __restrict__ Kh_g, const __nv_bfloat16* __restrict__ Kl_g,
              const __nv_bfloat16* __restrict__ Vh_g, const __nv_bfloat16* __restrict__ Vl_g,
              __nv_bfloat16* __restrict__ Oh_g, __nv_bfloat16* __restrict__ Ol_g)
{
    extern __shared__ char fsm[];
    __nv_bfloat16* Qh = (__nv_bfloat16*)(fsm + FO_QH);
    __nv_bfloat16* Ql = (__nv_bfloat16*)(fsm + FO_QL);
    __nv_bfloat16* Kh = (__nv_bfloat16*)(fsm + FO_KH);
    __nv_bfloat16* Kl = (__nv_bfloat16*)(fsm + FO_KL);
    __nv_bfloat16* Vh = (__nv_bfloat16*)(fsm + FO_VH);
    __nv_bfloat16* Vl = (__nv_bfloat16*)(fsm + FO_VL);
    __nv_bfloat16* Ph = (__nv_bfloat16*)(fsm + FO_PH);
    __nv_bfloat16* Pl = (__nv_bfloat16*)(fsm + FO_PL);
    float* Sf   = (float*)(fsm + FO_SF);
    float* mrow = (float*)(fsm + FO_MR);
    float* lrow = (float*)(fsm + FO_LR);
    float* crow = (float*)(fsm + FO_CR);

    const int qb = blockIdx.x, h = blockIdx.y, bb = blockIdx.z;
    const int tid = threadIdx.x;
    const int wid = tid >> 5;
    const int wm = (wid & 3) * 32;        // 4 m-warps
    const int wn = (wid >> 2) * 16;       // 4 n-warps
    const int q0 = qb * 128;
    const size_t base = (size_t)bb * SEQ * D_MODEL + (size_t)h * DKH;

    const int r  = tid >> 2;              // 0..127 (row owner)
    const int c0 = (tid & 3) * 16;        // 16-col slice

    // ---- load Q (bf16, direct) ----
    {
        const size_t g = base + (size_t)(q0 + r) * D_MODEL + c0;
        *(uint4*)(Qh + r * LDH + c0)     = *(const uint4*)(Qh_g + g);
        *(uint4*)(Qh + r * LDH + c0 + 8) = *(const uint4*)(Qh_g + g + 8);
        *(uint4*)(Ql + r * LDH + c0)     = *(const uint4*)(Ql_g + g);
        *(uint4*)(Ql + r * LDH + c0 + 8) = *(const uint4*)(Ql_g + g + 8);
    }
    if (tid < 128) { mrow[tid] = -INFINITY; lrow[tid] = 0.f; }

    float orow[16];
#pragma unroll
    for (int j = 0; j < 16; j++) orow[j] = 0.f;
    __syncthreads();

    const int kmax = 2 * qb + 1;          // last k-block index
    for (int kb = 0; kb <= kmax; kb++) {
        const int k0 = kb * 64;

        // ---- 1. load K, V (64 rows): thread -> one uint4 per tile ----
        {
            const int kr = tid >> 3;
            const int kc = (tid & 7) * 8;
            const size_t g = base + (size_t)(k0 + kr) * D_MODEL + kc;
            *(uint4*)(Kh + kr * LDH + kc) = *(const uint4*)(Kh_g + g);
            *(uint4*)(Kl + kr * LDH + kc) = *(const uint4*)(Kl_g + g);
            *(uint4*)(Vh + kr * LDH + kc) = *(const uint4*)(Vh_g + g);
            *(uint4*)(Vl + kr * LDH + kc) = *(const uint4*)(Vl_g + g);
        }
        __syncthreads();

        // ---- 2. S = Q K^T (128x64) ----
        {
            wmma::fragment<wmma::accumulator, 16, 16, 16, float> accS[2];
#pragma unroll
            for (int i = 0; i < 2; i++) wmma::fill_fragment(accS[i], 0.f);
#pragma unroll
            for (int ks = 0; ks < 64; ks += 16) {
                wmma::fragment<wmma::matrix_a, 16, 16, 16, __nv_bfloat16, wmma::row_major> ah[2], al[2];
                wmma::fragment<wmma::matrix_b, 16, 16, 16, __nv_bfloat16, wmma::col_major> bh, bl;
#pragma unroll
                for (int i = 0; i < 2; i++) {
                    wmma::load_matrix_sync(ah[i], Qh + (wm + i * 16) * LDH + ks, LDH);
                    wmma::load_matrix_sync(al[i], Ql + (wm + i * 16) * LDH + ks, LDH);
                }
                wmma::load_matrix_sync(bh, Kh + wn * LDH + ks, LDH);
                wmma::load_matrix_sync(bl, Kl + wn * LDH + ks, LDH);
#pragma unroll
                for (int i = 0; i < 2; i++) {
                    wmma::mma_sync(accS[i], ah[i], bh, accS[i]);
                    wmma::mma_sync(accS[i], ah[i], bl, accS[i]);
                    wmma::mma_sync(accS[i], al[i], bh, accS[i]);
                }
            }
#pragma unroll
            for (int i = 0; i < 2; i++)
                wmma::store_matrix_sync(Sf + (wm + i * 16) * LDF + wn, accS[i], LDF, wmma::mem_row_major);
        }
        __syncthreads();

        // ---- 3. softmax (4 threads / row) + split P ----
        {
            const bool needmask = (k0 + 63 > q0);
            const int qrow = q0 + r;
            float sv[16];
            const float* srow = Sf + r * LDF + c0;
            float mx = -INFINITY;
#pragma unroll
            for (int j = 0; j < 16; j++) {
                float v = srow[j] * 0.125f;
                if (needmask && (k0 + c0 + j) > qrow) v = -INFINITY;
                sv[j] = v;
                mx = fmaxf(mx, v);
            }
            mx = fmaxf(mx, __shfl_xor_sync(0xFFFFFFFFu, mx, 1));
            mx = fmaxf(mx, __shfl_xor_sync(0xFFFFFFFFu, mx, 2));
            const float mold = mrow[r];
            const float mnew = fmaxf(mold, mx);
            float lsum = 0.f;
#pragma unroll
            for (int j = 0; j < 16; j++) {
                float p = __expf(sv[j] - mnew);
                sv[j] = p;
                lsum += p;
            }
            lsum += __shfl_xor_sync(0xFFFFFFFFu, lsum, 1);
            lsum += __shfl_xor_sync(0xFFFFFFFFu, lsum, 2);
#pragma unroll
            for (int j = 0; j < 16; j += 2) {
                uint32_t hv, lv;
                split2(sv[j], sv[j + 1], hv, lv);
                *(uint32_t*)(Ph + r * LDH + c0 + j) = hv;
                *(uint32_t*)(Pl + r * LDH + c0 + j) = lv;
            }
            if ((tid & 3) == 0) {
                const float corr = __expf(mold - mnew);
                mrow[r] = mnew;
                lrow[r] = lrow[r] * corr + lsum;
                crow[r] = corr;
            }
        }
        __syncthreads();

        // ---- 4. PV = P @ V -> Sf ----
        {
            wmma::fragment<wmma::accumulator, 16, 16, 16, float> accO[2];
#pragma unroll
            for (int i = 0; i < 2; i++) wmma::fill_fragment(accO[i], 0.f);
#pragma unroll
            for (int ks = 0; ks < 64; ks += 16) {
                wmma::fragment<wmma::matrix_a, 16, 16, 16, __nv_bfloat16, wmma::row_major> ah[2], al[2];
                wmma::fragment<wmma::matrix_b, 16, 16, 16, __nv_bfloat16, wmma::row_major> bh, bl;
#pragma unroll
                for (int i = 0; i < 2; i++) {
                    wmma::load_matrix_sync(ah[i], Ph + (wm + i * 16) * LDH + ks, LDH);
                    wmma::load_matrix_sync(al[i], Pl + (wm + i * 16) * LDH + ks, LDH);
                }
                wmma::load_matrix_sync(bh, Vh + ks * LDH + wn, LDH);
                wmma::load_matrix_sync(bl, Vl + ks * LDH + wn, LDH);
#pragma unroll
                for (int i = 0; i < 2; i++) {
                    wmma::mma_sync(accO[i], ah[i], bh, accO[i]);
                    wmma::mma_sync(accO[i], ah[i], bl, accO[i]);
                    wmma::mma_sync(accO[i], al[i], bh, accO[i]);
                }
            }
#pragma unroll
            for (int i = 0; i < 2; i++)
                wmma::store_matrix_sync(Sf + (wm + i * 16) * LDF + wn, accO[i], LDF, wmma::mem_row_major);
        }
        __syncthreads();

        // ---- 5. O = O*corr + PV (registers) ----
        {
            const float corr = crow[r];
            const float* prow = Sf + r * LDF + c0;
#pragma unroll
            for (int j = 0; j < 16; j++) orow[j] = orow[j] * corr + prow[j];
        }
        __syncthreads();
    }

    // ---- final: normalize, split, store bf16 hi/lo ----
    {
        const float inv = 1.f / lrow[r];
        const size_t g = base + (size_t)(q0 + r) * D_MODEL + c0;
#pragma unroll
        for (int j = 0; j < 16; j += 2) {
            uint32_t hv, lv;
            split2(orow[j] * inv, orow[j + 1] * inv, hv, lv);
            *(uint32_t*)(Oh_g + g + j) = hv;
            *(uint32_t*)(Ol_g + g + j) = lv;
        }
    }
}

// ---------------- LayerNorm (ddof=1), optional hi/lo output ------------------
template <bool HL>
__global__ __launch_bounds__(256)
void layernorm_k(const float* __restrict__ in, const float* __restrict__ gamma,
                 const float* __restrict__ beta, float* __restrict__ out,
                 __nv_bfloat16* __restrict__ oh, __nv_bfloat16* __restrict__ ol)
{
    const int row = blockIdx.x;
    const int tid = threadIdx.x;
    const float4 v = ((const float4*)(in + (size_t)row * D_MODEL))[tid];
    float s  = v.x + v.y + v.z + v.w;
    float ss = v.x * v.x + v.y * v.y + v.z * v.z + v.w * v.w;

    __shared__ float rs[8], rss[8];
#pragma unroll
    for (int o = 16; o > 0; o >>= 1) {
        s  += __shfl_down_sync(0xFFFFFFFFu, s, o);
        ss += __shfl_down_sync(0xFFFFFFFFu, ss, o);
    }
    if ((tid & 31) == 0) { rs[tid >> 5] = s; rss[tid >> 5] = ss; }
    __syncthreads();
    float S = 0.f, SS = 0.f;
#pragma unroll
    for (int i = 0; i < 8; i++) { S += rs[i]; SS += rss[i]; }

    const float mean = S * (1.f / (float)D_MODEL);
    const float var  = (SS - (float)D_MODEL * mean * mean) * (1.f / (float)(D_MODEL - 1));
    const float inv  = rsqrtf(var + EPS_LN);

    const float4 g = ((const float4*)gamma)[tid];
    const float4 b = ((const float4*)beta)[tid];
    float4 o;
    o.x = g.x * (v.x - mean) * inv + b.x;
    o.y = g.y * (v.y - mean) * inv + b.y;
    o.z = g.z * (v.z - mean) * inv + b.z;
    o.w = g.w * (v.w - mean) * inv + b.w;
    ((float4*)(out + (size_t)row * D_MODEL))[tid] = o;
    if (HL) {
        uint32_t h01, l01, h23, l23;
        split2(o.x, o.y, h01, l01);
        split2(o.z, o.w, h23, l23);
        ((uint2*)(oh + (size_t)row * D_MODEL))[tid] = make_uint2(h01, h23);
        ((uint2*)(ol + (size_t)row * D_MODEL))[tid] = make_uint2(l01, l23);
    }
}

// ---------------- host launcher ---------------------------------------------
extern "C" void kernel_launch(void* const* d_in, const int* in_sizes, int n_in,
                              void* d_out, int out_size)
{
    (void)in_sizes; (void)n_in; (void)out_size;
    const float* x  = (const float*)d_in[0];
    const float* Wq = (const float*)d_in[2];
    const float* Wk = (const float*)d_in[3];
    const float* Wv = (const float*)d_in[4];
    const float* Wo = (const float*)d_in[5];
    const float* W1 = (const float*)d_in[6];
    const float* W2 = (const float*)d_in[7];
    const float* g1 = (const float*)d_in[8];
    const float* b1 = (const float*)d_in[9];
    const float* g2 = (const float*)d_in[10];
    const float* b2 = (const float*)d_in[11];
    float* out = (float*)d_out;

    __nv_bfloat16 *xh, *xl, *wqh, *wql, *wkh, *wkl, *wvh, *wvl, *woh, *wol;
    __nv_bfloat16 *w1h, *w1l, *w2h, *w2l;
    __nv_bfloat16 *qh, *ql, *kh, *kl, *vh, *vl, *ah, *al, *r1h, *r1l, *ffh, *ffl;
    float *tmp, *r1f, *tmp2;
    cudaGetSymbolAddress((void**)&xh, g_xh);   cudaGetSymbolAddress((void**)&xl, g_xl);
    cudaGetSymbolAddress((void**)&wqh, g_wqh); cudaGetSymbolAddress((void**)&wql, g_wql);
    cudaGetSymbolAddress((void**)&wkh, g_wkh); cudaGetSymbolAddress((void**)&wkl, g_wkl);
    cudaGetSymbolAddress((void**)&wvh, g_wvh); cudaGetSymbolAddress((void**)&wvl, g_wvl);
    cudaGetSymbolAddress((void**)&woh, g_woh); cudaGetSymbolAddress((void**)&wol, g_wol);
    cudaGetSymbolAddress((void**)&w1h, g_w1h); cudaGetSymbolAddress((void**)&w1l, g_w1l);
    cudaGetSymbolAddress((void**)&w2h, g_w2h); cudaGetSymbolAddress((void**)&w2l, g_w2l);
    cudaGetSymbolAddress((void**)&qh, g_qh);   cudaGetSymbolAddress((void**)&ql, g_ql);
    cudaGetSymbolAddress((void**)&kh, g_kh);   cudaGetSymbolAddress((void**)&kl, g_kl);
    cudaGetSymbolAddress((void**)&vh, g_vh);   cudaGetSymbolAddress((void**)&vl, g_vl);
    cudaGetSymbolAddress((void**)&ah, g_ah);   cudaGetSymbolAddress((void**)&al, g_al);
    cudaGetSymbolAddress((void**)&r1h, g_r1h); cudaGetSymbolAddress((void**)&r1l, g_r1l);
    cudaGetSymbolAddress((void**)&ffh, g_ffh); cudaGetSymbolAddress((void**)&ffl, g_ffl);
    cudaGetSymbolAddress((void**)&tmp, g_tmp);
    cudaGetSymbolAddress((void**)&r1f, g_r1f);
    cudaGetSymbolAddress((void**)&tmp2, g_tmp2);

    cudaFuncSetAttribute(gemm_bf<0,1>, cudaFuncAttributeMaxDynamicSharedMemorySize, GEMM_SMEM);
    cudaFuncSetAttribute(gemm_bf<1,1>, cudaFuncAttributeMaxDynamicSharedMemorySize, GEMM_SMEM);
    cudaFuncSetAttribute(gemm_bf<2,0>, cudaFuncAttributeMaxDynamicSharedMemorySize, GEMM_SMEM);
    cudaFuncSetAttribute(flash_bf, cudaFuncAttributeMaxDynamicSharedMemorySize, FA_SMEM);

    const dim3 blk(256);

    // ---- conversion passes ----
    cvt_hl<<<NELEM / 4 / 256, blk>>>(x,  xh,  xl,  NELEM / 4);
    cvt_hl<<<WELEM / 4 / 256, blk>>>(Wq, wqh, wql, WELEM / 4);
    cvt_hl<<<WELEM / 4 / 256, blk>>>(Wk, wkh, wkl, WELEM / 4);
    cvt_hl<<<WELEM / 4 / 256, blk>>>(Wv, wvh, wvl, WELEM / 4);
    cvt_hl<<<WELEM / 4 / 256, blk>>>(Wo, woh, wol, WELEM / 4);
    cvt_hl<<<FELEM / 4 / 256, blk>>>(W1, w1h, w1l, FELEM / 4);
    cvt_hl<<<FELEM / 4 / 256, blk>>>(W2, w2h, w2l, FELEM / 4);

    const dim3 gD(D_MODEL / 128, MROWS / 128);   // (8, 32)
    const dim3 gF(D_FF / 128, MROWS / 128);      // (32, 32)

    // QKV projections -> bf16 hi/lo
    gemm_bf<0,1><<<gD, blk, GEMM_SMEM>>>(xh, xl, wqh, wql, nullptr, nullptr, qh, ql, MROWS, D_MODEL, D_MODEL);
    gemm_bf<0,1><<<gD, blk, GEMM_SMEM>>>(xh, xl, wkh, wkl, nullptr, nullptr, kh, kl, MROWS, D_MODEL, D_MODEL);
    gemm_bf<0,1><<<gD, blk, GEMM_SMEM>>>(xh, xl, wvh, wvl, nullptr, nullptr, vh, vl, MROWS, D_MODEL, D_MODEL);

    // Flash attention (bf16 in/out)
    flash_bf<<<dim3(SEQ / 128, HEADS, BATCH), dim3(512), FA_SMEM>>>(qh, ql, kh, kl, vh, vl, ah, al);

    // Output projection + residual x -> fp32, then LN1 (fp32 + hi/lo)
    gemm_bf<2,0><<<gD, blk, GEMM_SMEM>>>(ah, al, woh, wol, x, tmp, nullptr, nullptr, MROWS, D_MODEL, D_MODEL);
    layernorm_k<true><<<MROWS, blk>>>(tmp, g1, b1, r1f, r1h, r1l);

    // FFN
    gemm_bf<1,1><<<gF, blk, GEMM_SMEM>>>(r1h, r1l, w1h, w1l, nullptr, nullptr, ffh, ffl, MROWS, D_FF, D_MODEL);
    gemm_bf<2,0><<<gD, blk, GEMM_SMEM>>>(ffh, ffl, w2h, w2l, r1f, tmp2, nullptr, nullptr, MROWS, D_MODEL, D_FF);
    layernorm_k<false><<<MROWS, blk>>>(tmp2, g2, b2, out, nullptr, nullptr);
}

// round 9
// speedup vs baseline: 2.2293x; 1.0638x over previous
#include <cuda_runtime.h>
#include <cuda_bf16.h>
#include <mma.h>
#include <math.h>
#include <stdint.h>

using namespace nvcuda;

#define D_MODEL 1024
#define HEADS   16
#define DKH     64
#define D_FF    4096
#define BATCH   2
#define SEQ     2048
#define MROWS   (BATCH * SEQ)   // 4096
#define EPS_LN  1e-6f
#define NELEM   (MROWS * D_MODEL)
#define WELEM   (D_MODEL * D_MODEL)
#define FELEM   (D_FF * D_MODEL)
#define FFELEM  (MROWS * D_FF)

// ---------------- scratch (static device globals; no allocs) ----------------
__device__ __nv_bfloat16 g_xh[NELEM],  g_xl[NELEM];
__device__ __nv_bfloat16 g_wqh[WELEM], g_wql[WELEM];
__device__ __nv_bfloat16 g_wkh[WELEM], g_wkl[WELEM];
__device__ __nv_bfloat16 g_wvh[WELEM], g_wvl[WELEM];
__device__ __nv_bfloat16 g_woh[WELEM], g_wol[WELEM];
__device__ __nv_bfloat16 g_w1h[FELEM], g_w1l[FELEM];
__device__ __nv_bfloat16 g_w2h[FELEM], g_w2l[FELEM];
__device__ __nv_bfloat16 g_qh[NELEM],  g_ql[NELEM];
__device__ __nv_bfloat16 g_kh[NELEM],  g_kl[NELEM];
__device__ __nv_bfloat16 g_vh[NELEM],  g_vl[NELEM];
__device__ __nv_bfloat16 g_ah[NELEM],  g_al[NELEM];
__device__ __nv_bfloat16 g_r1h[NELEM], g_r1l[NELEM];
__device__ __nv_bfloat16 g_ffh[FFELEM], g_ffl[FFELEM];
__device__ float g_tmp[NELEM];
__device__ float g_r1f[NELEM];
__device__ float g_tmp2[NELEM];

// ================= helpers ===================================================
__device__ __forceinline__ void split2(float a, float b, uint32_t& hi, uint32_t& lo) {
    __nv_bfloat16 ha = __float2bfloat16_rn(a);
    __nv_bfloat16 hb = __float2bfloat16_rn(b);
    float la = a - __bfloat162float(ha);
    float lb = b - __bfloat162float(hb);
    __nv_bfloat162 hv = __halves2bfloat162(ha, hb);
    __nv_bfloat162 lv = __floats2bfloat162_rn(la, lb);
    hi = *reinterpret_cast<uint32_t*>(&hv);
    lo = *reinterpret_cast<uint32_t*>(&lv);
}

#define CP16(dst, src) \
    asm volatile("cp.async.cg.shared.global [%0], [%1], 16;" :: \
        "r"((uint32_t)__cvta_generic_to_shared(dst)), "l"(src))
#define CP_COMMIT() asm volatile("cp.async.commit_group;" ::: "memory")
#define CP_WAIT(n)  asm volatile("cp.async.wait_group %0;" :: "n"(n) : "memory")

// ---------------- fp32 -> bf16 hi/lo conversion ------------------------------
__global__ __launch_bounds__(256)
void cvt_hl(const float* __restrict__ src, __nv_bfloat16* __restrict__ hi,
            __nv_bfloat16* __restrict__ lo, int n4)
{
    int i = blockIdx.x * 256 + threadIdx.x;
    if (i < n4) {
        float4 v = ((const float4*)src)[i];
        uint32_t h01, l01, h23, l23;
        split2(v.x, v.y, h01, l01);
        split2(v.z, v.w, h23, l23);
        ((uint2*)hi)[i] = make_uint2(h01, h23);
        ((uint2*)lo)[i] = make_uint2(l01, l23);
    }
}

// ================= WMMA GEMM: C = A @ B^T (+epilogue), bf16x3 ================
// k-chunk 64, 3-stage cp.async pipeline. LDT=72 (conflict-free).
// EPI: 0 none, 1 relu, 2 residual. OUT: 0 fp32, 1 bf16 hi/lo. QKV: fused 3-dest.
#define GLDT    72
#define GTILE   (128 * GLDT)                 // 9216 elems
#define GSTAGE  (4 * GTILE)                  // Ah,Al,Bh,Bl = 36864 elems
#define GSTAGES 3
#define GEMM_SMEM (GSTAGES * GSTAGE * 2)     // 221184 B

__device__ __forceinline__ void gemm_issue(__nv_bfloat16* st,
    const __nv_bfloat16* Ahg, const __nv_bfloat16* Alg,
    const __nv_bfloat16* Bhg, const __nv_bfloat16* Blg,
    int K, int k0, int tid)
{
    const __nv_bfloat16* srcs[4] = {Ahg, Alg, Bhg, Blg};
#pragma unroll
    for (int tile = 0; tile < 4; tile++) {
        __nv_bfloat16* dst = st + tile * GTILE;
        const __nv_bfloat16* g = srcs[tile];
#pragma unroll
        for (int it = 0; it < 4; it++) {
            int ch = tid + it * 256;          // 0..1023
            int r = ch >> 3;                  // 0..127
            int c = (ch & 7) * 8;             // 0..56
            CP16(dst + r * GLDT + c, g + (size_t)r * K + k0 + c);
        }
    }
}

template <int EPI, int OUT, int QKV>
__global__ __launch_bounds__(256)
void gemm_bf(const __nv_bfloat16* __restrict__ Ah, const __nv_bfloat16* __restrict__ Al,
             const __nv_bfloat16* __restrict__ Bh_, const __nv_bfloat16* __restrict__ Bl_,
             const __nv_bfloat16* __restrict__ Bh2, const __nv_bfloat16* __restrict__ Bl2,
             const __nv_bfloat16* __restrict__ Bh3, const __nv_bfloat16* __restrict__ Bl3,
             const float* __restrict__ Rf, float* __restrict__ Cf,
             __nv_bfloat16* __restrict__ Ch_, __nv_bfloat16* __restrict__ Cl_,
             __nv_bfloat16* __restrict__ Ch2, __nv_bfloat16* __restrict__ Cl2,
             __nv_bfloat16* __restrict__ Ch3, __nv_bfloat16* __restrict__ Cl3,
             int M, int N, int K)
{
    extern __shared__ __nv_bfloat16 sh[];

    const int tid = threadIdx.x;
    const int wid = tid >> 5;
    const int wm = (wid & 3) * 32;
    const int wn = (wid >> 2) * 64;

    const __nv_bfloat16* Bh = Bh_;
    const __nv_bfloat16* Bl = Bl_;
    __nv_bfloat16* Ch = Ch_;
    __nv_bfloat16* Cl = Cl_;
    int col0;
    if (QKV) {
        const int mat = blockIdx.x >> 3;      // 0,1,2 -> q,k,v
        col0 = (blockIdx.x & 7) * 128;
        if (mat == 1) { Bh = Bh2; Bl = Bl2; Ch = Ch2; Cl = Cl2; }
        else if (mat == 2) { Bh = Bh3; Bl = Bl3; Ch = Ch3; Cl = Cl3; }
    } else {
        col0 = blockIdx.x * 128;
    }
    const int row0 = blockIdx.y * 128;
    const __nv_bfloat16* Ahg = Ah + (size_t)row0 * K;
    const __nv_bfloat16* Alg = Al + (size_t)row0 * K;
    const __nv_bfloat16* Bhg = Bh + (size_t)col0 * K;
    const __nv_bfloat16* Blg = Bl + (size_t)col0 * K;

    wmma::fragment<wmma::accumulator, 16, 16, 16, float> acc[2][4];
#pragma unroll
    for (int i = 0; i < 2; i++)
#pragma unroll
        for (int j = 0; j < 4; j++) wmma::fill_fragment(acc[i][j], 0.f);

    const int T = K / 64;
    gemm_issue(sh, Ahg, Alg, Bhg, Blg, K, 0, tid);
    CP_COMMIT();
    gemm_issue(sh + GSTAGE, Ahg, Alg, Bhg, Blg, K, 64, tid);
    CP_COMMIT();

    for (int t = 0; t < T; t++) {
        if (t + 1 < T) { CP_WAIT(1); } else { CP_WAIT(0); }
        __syncthreads();
        if (t + 2 < T) {
            gemm_issue(sh + ((t + 2) % GSTAGES) * GSTAGE, Ahg, Alg, Bhg, Blg,
                       K, (t + 2) * 64, tid);
            CP_COMMIT();
        }
        __nv_bfloat16* Ahs = sh + (t % GSTAGES) * GSTAGE;
        __nv_bfloat16* Als = Ahs + GTILE;
        __nv_bfloat16* Bhs = Ahs + 2 * GTILE;
        __nv_bfloat16* Bls = Ahs + 3 * GTILE;
#pragma unroll
        for (int ks = 0; ks < 64; ks += 16) {
            wmma::fragment<wmma::matrix_a, 16, 16, 16, __nv_bfloat16, wmma::row_major> a_hi[2], a_lo[2];
            wmma::fragment<wmma::matrix_b, 16, 16, 16, __nv_bfloat16, wmma::col_major> b_hi[4], b_lo[4];
#pragma unroll
            for (int i = 0; i < 2; i++) {
                wmma::load_matrix_sync(a_hi[i], Ahs + (wm + i * 16) * GLDT + ks, GLDT);
                wmma::load_matrix_sync(a_lo[i], Als + (wm + i * 16) * GLDT + ks, GLDT);
            }
#pragma unroll
            for (int j = 0; j < 4; j++) {
                wmma::load_matrix_sync(b_hi[j], Bhs + (wn + j * 16) * GLDT + ks, GLDT);
                wmma::load_matrix_sync(b_lo[j], Bls + (wn + j * 16) * GLDT + ks, GLDT);
            }
#pragma unroll
            for (int i = 0; i < 2; i++) {
#pragma unroll
                for (int j = 0; j < 4; j++) {
                    wmma::mma_sync(acc[i][j], a_hi[i], b_hi[j], acc[i][j]);
                    wmma::mma_sync(acc[i][j], a_hi[i], b_lo[j], acc[i][j]);
                    wmma::mma_sync(acc[i][j], a_lo[i], b_hi[j], acc[i][j]);
                }
            }
        }
    }

    if (OUT == 0) {
#pragma unroll
        for (int i = 0; i < 2; i++) {
#pragma unroll
            for (int j = 0; j < 4; j++) {
                const int row = row0 + wm + i * 16;
                const int col = col0 + wn + j * 16;
                if (EPI == 2) {
                    wmma::fragment<wmma::accumulator, 16, 16, 16, float> rf;
                    wmma::load_matrix_sync(rf, Rf + (size_t)row * N + col, N, wmma::mem_row_major);
#pragma unroll
                    for (int e = 0; e < rf.num_elements; e++) acc[i][j].x[e] += rf.x[e];
                }
                if (EPI == 1) {
#pragma unroll
                    for (int e = 0; e < acc[i][j].num_elements; e++)
                        acc[i][j].x[e] = fmaxf(acc[i][j].x[e], 0.f);
                }
                wmma::store_matrix_sync(Cf + (size_t)row * N + col, acc[i][j], N, wmma::mem_row_major);
            }
        }
    } else {
        float* stg = (float*)sh;              // 128 x 132 fp32 staging
        __syncthreads();
#pragma unroll
        for (int i = 0; i < 2; i++) {
#pragma unroll
            for (int j = 0; j < 4; j++) {
                if (EPI == 1) {
#pragma unroll
                    for (int e = 0; e < acc[i][j].num_elements; e++)
                        acc[i][j].x[e] = fmaxf(acc[i][j].x[e], 0.f);
                }
                wmma::store_matrix_sync(stg + (wm + i * 16) * 132 + wn + j * 16,
                                        acc[i][j], 132, wmma::mem_row_major);
            }
        }
        __syncthreads();
        const int r = tid >> 1;
        const int cb = (tid & 1) * 64;
#pragma unroll
        for (int j = 0; j < 64; j += 4) {
            float4 v = *(const float4*)(stg + r * 132 + cb + j);
            uint32_t h01, l01, h23, l23;
            split2(v.x, v.y, h01, l01);
            split2(v.z, v.w, h23, l23);
            const size_t off = (size_t)(row0 + r) * N + col0 + cb + j;
            *(uint2*)(Ch + off) = make_uint2(h01, h23);
            *(uint2*)(Cl + off) = make_uint2(l01, l23);
        }
    }
}

// ================= WMMA flash attention (bf16x3 in/out, fp32 softmax) ========
#define LDH 72
#define LDF 68
#define FO_QH 0
#define FO_QL (FO_QH + 128 * LDH * 2)
#define FO_KH (FO_QL + 128 * LDH * 2)
#define FO_KL (FO_KH + 64 * LDH * 2)
#define FO_VH (FO_KL + 64 * LDH * 2)
#define FO_VL (FO_VH + 64 * LDH * 2)
#define FO_PH (FO_VL + 64 * LDH * 2)
#define FO_PL (FO_PH + 128 * LDH * 2)
#define FO_SF (FO_PL + 128 * LDH * 2)
#define FO_MR (FO_SF + 128 * LDF * 4)
#define FO_LR (FO_MR + 512)
#define FO_CR (FO_LR + 512)
#define FA_SMEM (FO_CR + 512)             // 146944 B

__global__ __launch_bounds__(512)
void flash_bf(const __nv_bfloat16* __restrict__ Qh_g, const __nv_bfloat16* __restrict__ Ql_g,
              const __nv_bfloat16* __restrict__ Kh_g, const __nv_bfloat16* __restrict__ Kl_g,
              const __nv_bfloat16* __restrict__ Vh_g, const __nv_bfloat16* __restrict__ Vl_g,
              __nv_bfloat16* __restrict__ Oh_g, __nv_bfloat16* __restrict__ Ol_g)
{
    extern __shared__ char fsm[];
    __nv_bfloat16* Qh = (__nv_bfloat16*)(fsm + FO_QH);
    __nv_bfloat16* Ql = (__nv_bfloat16*)(fsm + FO_QL);
    __nv_bfloat16* Kh = (__nv_bfloat16*)(fsm + FO_KH);
    __nv_bfloat16* Kl = (__nv_bfloat16*)(fsm + FO_KL);
    __nv_bfloat16* Vh = (__nv_bfloat16*)(fsm + FO_VH);
    __nv_bfloat16* Vl = (__nv_bfloat16*)(fsm + FO_VL);
    __nv_bfloat16* Ph = (__nv_bfloat16*)(fsm + FO_PH);
    __nv_bfloat16* Pl = (__nv_bfloat16*)(fsm + FO_PL);
    float* Sf   = (float*)(fsm + FO_SF);
    float* mrow = (float*)(fsm + FO_MR);
    float* lrow = (float*)(fsm + FO_LR);
    float* crow = (float*)(fsm + FO_CR);

    // heavy q-blocks first for better wave packing
    const int qb = gridDim.x - 1 - blockIdx.x;
    const int h = blockIdx.y, bb = blockIdx.z;
    const int tid = threadIdx.x;
    const int wid = tid >> 5;
    const int wm = (wid & 3) * 32;
    const int wn = (wid >> 2) * 16;
    const int q0 = qb * 128;
    const size_t base = (size_t)bb * SEQ * D_MODEL + (size_t)h * DKH;

    const int r  = tid >> 2;
    const int c0 = (tid & 3) * 16;

    {
        const size_t g = base + (size_t)(q0 + r) * D_MODEL + c0;
        *(uint4*)(Qh + r * LDH + c0)     = *(const uint4*)(Qh_g + g);
        *(uint4*)(Qh + r * LDH + c0 + 8) = *(const uint4*)(Qh_g + g + 8);
        *(uint4*)(Ql + r * LDH + c0)     = *(const uint4*)(Ql_g + g);
        *(uint4*)(Ql + r * LDH + c0 + 8) = *(const uint4*)(Ql_g + g + 8);
    }
    if (tid < 128) { mrow[tid] = -INFINITY; lrow[tid] = 0.f; }

    float orow[16];
#pragma unroll
    for (int j = 0; j < 16; j++) orow[j] = 0.f;
    __syncthreads();

    const int kmax = 2 * qb + 1;
    for (int kb = 0; kb <= kmax; kb++) {
        const int k0 = kb * 64;

        {
            const int kr = tid >> 3;
            const int kc = (tid & 7) * 8;
            const size_t g = base + (size_t)(k0 + kr) * D_MODEL + kc;
            *(uint4*)(Kh + kr * LDH + kc) = *(const uint4*)(Kh_g + g);
            *(uint4*)(Kl + kr * LDH + kc) = *(const uint4*)(Kl_g + g);
            *(uint4*)(Vh + kr * LDH + kc) = *(const uint4*)(Vh_g + g);
            *(uint4*)(Vl + kr * LDH + kc) = *(const uint4*)(Vl_g + g);
        }
        __syncthreads();

        {
            wmma::fragment<wmma::accumulator, 16, 16, 16, float> accS[2];
#pragma unroll
            for (int i = 0; i < 2; i++) wmma::fill_fragment(accS[i], 0.f);
#pragma unroll
            for (int ks = 0; ks < 64; ks += 16) {
                wmma::fragment<wmma::matrix_a, 16, 16, 16, __nv_bfloat16, wmma::row_major> ah[2], al[2];
                wmma::fragment<wmma::matrix_b, 16, 16, 16, __nv_bfloat16, wmma::col_major> bh, bl;
#pragma unroll
                for (int i = 0; i < 2; i++) {
                    wmma::load_matrix_sync(ah[i], Qh + (wm + i * 16) * LDH + ks, LDH);
                    wmma::load_matrix_sync(al[i], Ql + (wm + i * 16) * LDH + ks, LDH);
                }
                wmma::load_matrix_sync(bh, Kh + wn * LDH + ks, LDH);
                wmma::load_matrix_sync(bl, Kl + wn * LDH + ks, LDH);
#pragma unroll
                for (int i = 0; i < 2; i++) {
                    wmma::mma_sync(accS[i], ah[i], bh, accS[i]);
                    wmma::mma_sync(accS[i], ah[i], bl, accS[i]);
                    wmma::mma_sync(accS[i], al[i], bh, accS[i]);
                }
            }
#pragma unroll
            for (int i = 0; i < 2; i++)
                wmma::store_matrix_sync(Sf + (wm + i * 16) * LDF + wn, accS[i], LDF, wmma::mem_row_major);
        }
        __syncthreads();

        {
            const bool needmask = (k0 + 63 > q0);
            const int qrow = q0 + r;
            float sv[16];
            const float* srow = Sf + r * LDF + c0;
            float mx = -INFINITY;
#pragma unroll
            for (int j = 0; j < 16; j++) {
                float v = srow[j] * 0.125f;
                if (needmask && (k0 + c0 + j) > qrow) v = -INFINITY;
                sv[j] = v;
                mx = fmaxf(mx, v);
            }
            mx = fmaxf(mx, __shfl_xor_sync(0xFFFFFFFFu, mx, 1));
            mx = fmaxf(mx, __shfl_xor_sync(0xFFFFFFFFu, mx, 2));
            const float mold = mrow[r];
            const float mnew = fmaxf(mold, mx);
            float lsum = 0.f;
#pragma unroll
            for (int j = 0; j < 16; j++) {
                float p = __expf(sv[j] - mnew);
                sv[j] = p;
                lsum += p;
            }
            lsum += __shfl_xor_sync(0xFFFFFFFFu, lsum, 1);
            lsum += __shfl_xor_sync(0xFFFFFFFFu, lsum, 2);
#pragma unroll
            for (int j = 0; j < 16; j += 2) {
                uint32_t hv, lv;
                split2(sv[j], sv[j + 1], hv, lv);
                *(uint32_t*)(Ph + r * LDH + c0 + j) = hv;
                *(uint32_t*)(Pl + r * LDH + c0 + j) = lv;
            }
            if ((tid & 3) == 0) {
                const float corr = __expf(mold - mnew);
                mrow[r] = mnew;
                lrow[r] = lrow[r] * corr + lsum;
                crow[r] = corr;
            }
        }
        __syncthreads();

        {
            wmma::fragment<wmma::accumulator, 16, 16, 16, float> accO[2];
#pragma unroll
            for (int i = 0; i < 2; i++) wmma::fill_fragment(accO[i], 0.f);
#pragma unroll
            for (int ks = 0; ks < 64; ks += 16) {
                wmma::fragment<wmma::matrix_a, 16, 16, 16, __nv_bfloat16, wmma::row_major> ah[2], al[2];
                wmma::fragment<wmma::matrix_b, 16, 16, 16, __nv_bfloat16, wmma::row_major> bh, bl;
#pragma unroll
                for (int i = 0; i < 2; i++) {
                    wmma::load_matrix_sync(ah[i], Ph + (wm + i * 16) * LDH + ks, LDH);
                    wmma::load_matrix_sync(al[i], Pl + (wm + i * 16) * LDH + ks, LDH);
                }
                wmma::load_matrix_sync(bh, Vh + ks * LDH + wn, LDH);
                wmma::load_matrix_sync(bl, Vl + ks * LDH + wn, LDH);
#pragma unroll
                for (int i = 0; i < 2; i++) {
                    wmma::mma_sync(accO[i], ah[i], bh, accO[i]);
                    wmma::mma_sync(accO[i], ah[i], bl, accO[i]);
                    wmma::mma_sync(accO[i], al[i], bh, accO[i]);
                }
            }
#pragma unroll
            for (int i = 0; i < 2; i++)
                wmma::store_matrix_sync(Sf + (wm + i * 16) * LDF + wn, accO[i], LDF, wmma::mem_row_major);
        }
        __syncthreads();

        {
            const float corr = crow[r];
            const float* prow = Sf + r * LDF + c0;
#pragma unroll
            for (int j = 0; j < 16; j++) orow[j] = orow[j] * corr + prow[j];
        }
        __syncthreads();
    }

    {
        const float inv = 1.f / lrow[r];
        const size_t g = base + (size_t)(q0 + r) * D_MODEL + c0;
#pragma unroll
        for (int j = 0; j < 16; j += 2) {
            uint32_t hv, lv;
            split2(orow[j] * inv, orow[j + 1] * inv, hv, lv);
            *(uint32_t*)(Oh_g + g + j) = hv;
            *(uint32_t*)(Ol_g + g + j) = lv;
        }
    }
}

// ---------------- LayerNorm (ddof=1), optional hi/lo output ------------------
template <bool HL>
__global__ __launch_bounds__(256)
void layernorm_k(const float* __restrict__ in, const float* __restrict__ gamma,
                 const float* __restrict__ beta, float* __restrict__ out,
                 __nv_bfloat16* __restrict__ oh, __nv_bfloat16* __restrict__ ol)
{
    const int row = blockIdx.x;
    const int tid = threadIdx.x;
    const float4 v = ((const float4*)(in + (size_t)row * D_MODEL))[tid];
    float s  = v.x + v.y + v.z + v.w;
    float ss = v.x * v.x + v.y * v.y + v.z * v.z + v.w * v.w;

    __shared__ float rs[8], rss[8];
#pragma unroll
    for (int o = 16; o > 0; o >>= 1) {
        s  += __shfl_down_sync(0xFFFFFFFFu, s, o);
        ss += __shfl_down_sync(0xFFFFFFFFu, ss, o);
    }
    if ((tid & 31) == 0) { rs[tid >> 5] = s; rss[tid >> 5] = ss; }
    __syncthreads();
    float S = 0.f, SS = 0.f;
#pragma unroll
    for (int i = 0; i < 8; i++) { S += rs[i]; SS += rss[i]; }

    const float mean = S * (1.f / (float)D_MODEL);
    const float var  = (SS - (float)D_MODEL * mean * mean) * (1.f / (float)(D_MODEL - 1));
    const float inv  = rsqrtf(var + EPS_LN);

    const float4 g = ((const float4*)gamma)[tid];
    const float4 b = ((const float4*)beta)[tid];
    float4 o;
    o.x = g.x * (v.x - mean) * inv + b.x;
    o.y = g.y * (v.y - mean) * inv + b.y;
    o.z = g.z * (v.z - mean) * inv + b.z;
    o.w = g.w * (v.w - mean) * inv + b.w;
    ((float4*)(out + (size_t)row * D_MODEL))[tid] = o;
    if (HL) {
        uint32_t h01, l01, h23, l23;
        split2(o.x, o.y, h01, l01);
        split2(o.z, o.w, h23, l23);
        ((uint2*)(oh + (size_t)row * D_MODEL))[tid] = make_uint2(h01, h23);
        ((uint2*)(ol + (size_t)row * D_MODEL))[tid] = make_uint2(l01, l23);
    }
}

// ---------------- host launcher ---------------------------------------------
extern "C" void kernel_launch(void* const* d_in, const int* in_sizes, int n_in,
                              void* d_out, int out_size)
{
    (void)in_sizes; (void)n_in; (void)out_size;
    const float* x  = (const float*)d_in[0];
    const float* Wq = (const float*)d_in[2];
    const float* Wk = (const float*)d_in[3];
    const float* Wv = (const float*)d_in[4];
    const float* Wo = (const float*)d_in[5];
    const float* W1 = (const float*)d_in[6];
    const float* W2 = (const float*)d_in[7];
    const float* g1 = (const float*)d_in[8];
    const float* b1 = (const float*)d_in[9];
    const float* g2 = (const float*)d_in[10];
    const float* b2 = (const float*)d_in[11];
    float* out = (float*)d_out;

    __nv_bfloat16 *xh, *xl, *wqh, *wql, *wkh, *wkl, *wvh, *wvl, *woh, *wol;
    __nv_bfloat16 *w1h, *w1l, *w2h, *w2l;
    __nv_bfloat16 *qh, *ql, *kh, *kl, *vh, *vl, *ah, *al, *r1h, *r1l, *ffh, *ffl;
    float *tmp, *r1f, *tmp2;
    cudaGetSymbolAddress((void**)&xh, g_xh);   cudaGetSymbolAddress((void**)&xl, g_xl);
    cudaGetSymbolAddress((void**)&wqh, g_wqh); cudaGetSymbolAddress((void**)&wql, g_wql);
    cudaGetSymbolAddress((void**)&wkh, g_wkh); cudaGetSymbolAddress((void**)&wkl, g_wkl);
    cudaGetSymbolAddress((void**)&wvh, g_wvh); cudaGetSymbolAddress((void**)&wvl, g_wvl);
    cudaGetSymbolAddress((void**)&woh, g_woh); cudaGetSymbolAddress((void**)&wol, g_wol);
    cudaGetSymbolAddress((void**)&w1h, g_w1h); cudaGetSymbolAddress((void**)&w1l, g_w1l);
    cudaGetSymbolAddress((void**)&w2h, g_w2h); cudaGetSymbolAddress((void**)&w2l, g_w2l);
    cudaGetSymbolAddress((void**)&qh, g_qh);   cudaGetSymbolAddress((void**)&ql, g_ql);
    cudaGetSymbolAddress((void**)&kh, g_kh);   cudaGetSymbolAddress((void**)&kl, g_kl);
    cudaGetSymbolAddress((void**)&vh, g_vh);   cudaGetSymbolAddress((void**)&vl, g_vl);
    cudaGetSymbolAddress((void**)&ah, g_ah);   cudaGetSymbolAddress((void**)&al, g_al);
    cudaGetSymbolAddress((void**)&r1h, g_r1h); cudaGetSymbolAddress((void**)&r1l, g_r1l);
    cudaGetSymbolAddress((void**)&ffh, g_ffh); cudaGetSymbolAddress((void**)&ffl, g_ffl);
    cudaGetSymbolAddress((void**)&tmp, g_tmp);
    cudaGetSymbolAddress((void**)&r1f, g_r1f);
    cudaGetSymbolAddress((void**)&tmp2, g_tmp2);

    cudaFuncSetAttribute(gemm_bf<0,1,1>, cudaFuncAttributeMaxDynamicSharedMemorySize, GEMM_SMEM);
    cudaFuncSetAttribute(gemm_bf<1,1,0>, cudaFuncAttributeMaxDynamicSharedMemorySize, GEMM_SMEM);
    cudaFuncSetAttribute(gemm_bf<2,0,0>, cudaFuncAttributeMaxDynamicSharedMemorySize, GEMM_SMEM);
    cudaFuncSetAttribute(flash_bf, cudaFuncAttributeMaxDynamicSharedMemorySize, FA_SMEM);

    const dim3 blk(256);

    // ---- conversion passes ----
    cvt_hl<<<NELEM / 4 / 256, blk>>>(x,  xh,  xl,  NELEM / 4);
    cvt_hl<<<WELEM / 4 / 256, blk>>>(Wq, wqh, wql, WELEM / 4);
    cvt_hl<<<WELEM / 4 / 256, blk>>>(Wk, wkh, wkl, WELEM / 4);
    cvt_hl<<<WELEM / 4 / 256, blk>>>(Wv, wvh, wvl, WELEM / 4);
    cvt_hl<<<WELEM / 4 / 256, blk>>>(Wo, woh, wol, WELEM / 4);
    cvt_hl<<<FELEM / 4 / 256, blk>>>(W1, w1h, w1l, FELEM / 4);
    cvt_hl<<<FELEM / 4 / 256, blk>>>(W2, w2h, w2l, FELEM / 4);

    const dim3 gQKV(24, MROWS / 128);            // fused QKV
    const dim3 gD(D_MODEL / 128, MROWS / 128);   // (8, 32)
    const dim3 gF(D_FF / 128, MROWS / 128);      // (32, 32)

    // Fused QKV projection -> bf16 hi/lo
    gemm_bf<0,1,1><<<gQKV, blk, GEMM_SMEM>>>(xh, xl, wqh, wql, wkh, wkl, wvh, wvl,
                                             nullptr, nullptr, qh, ql, kh, kl, vh, vl,
                                             MROWS, D_MODEL, D_MODEL);

    // Flash attention (bf16 in/out)
    flash_bf<<<dim3(SEQ / 128, HEADS, BATCH), dim3(512), FA_SMEM>>>(qh, ql, kh, kl, vh, vl, ah, al);

    // Output projection + residual x -> fp32, then LN1 (fp32 + hi/lo)
    gemm_bf<2,0,0><<<gD, blk, GEMM_SMEM>>>(ah, al, woh, wol, nullptr, nullptr, nullptr, nullptr,
                                           x, tmp, nullptr, nullptr, nullptr, nullptr, nullptr, nullptr,
                                           MROWS, D_MODEL, D_MODEL);
    layernorm_k<true><<<MROWS, blk>>>(tmp, g1, b1, r1f, r1h, r1l);

    // FFN
    gemm_bf<1,1,0><<<gF, blk, GEMM_SMEM>>>(r1h, r1l, w1h, w1l, nullptr, nullptr, nullptr, nullptr,
                                           nullptr, nullptr, ffh, ffl, nullptr, nullptr, nullptr, nullptr,
                                           MROWS, D_FF, D_MODEL);
    gemm_bf<2,0,0><<<gD, blk, GEMM_SMEM>>>(ffh, ffl, w2h, w2l, nullptr, nullptr, nullptr, nullptr,
                                           r1f, tmp2, nullptr, nullptr, nullptr, nullptr, nullptr, nullptr,
                                           MROWS, D_MODEL, D_FF);
    layernorm_k<false><<<MROWS, blk>>>(tmp2, g2, b2, out, nullptr, nullptr);
}

// round 10
// speedup vs baseline: 2.2726x; 1.0194x over previous
#include <cuda_runtime.h>
#include <cuda_bf16.h>
#include <mma.h>
#include <math.h>
#include <stdint.h>

using namespace nvcuda;

#define D_MODEL 1024
#define HEADS   16
#define DKH     64
#define D_FF    4096
#define BATCH   2
#define SEQ     2048
#define MROWS   (BATCH * SEQ)   // 4096
#define EPS_LN  1e-6f
#define NELEM   (MROWS * D_MODEL)
#define WELEM   (D_MODEL * D_MODEL)
#define FELEM   (D_FF * D_MODEL)
#define FFELEM  (MROWS * D_FF)

// ---------------- scratch (static device globals; no allocs) ----------------
__device__ __nv_bfloat16 g_xh[NELEM],  g_xl[NELEM];
__device__ __nv_bfloat16 g_wqh[WELEM], g_wql[WELEM];
__device__ __nv_bfloat16 g_wkh[WELEM], g_wkl[WELEM];
__device__ __nv_bfloat16 g_wvh[WELEM], g_wvl[WELEM];
__device__ __nv_bfloat16 g_woh[WELEM], g_wol[WELEM];
__device__ __nv_bfloat16 g_w1h[FELEM], g_w1l[FELEM];
__device__ __nv_bfloat16 g_w2h[FELEM], g_w2l[FELEM];
__device__ __nv_bfloat16 g_qh[NELEM],  g_ql[NELEM];
__device__ __nv_bfloat16 g_kh[NELEM],  g_kl[NELEM];
__device__ __nv_bfloat16 g_vh[NELEM],  g_vl[NELEM];
__device__ __nv_bfloat16 g_ah[NELEM],  g_al[NELEM];
__device__ __nv_bfloat16 g_r1h[NELEM], g_r1l[NELEM];
__device__ __nv_bfloat16 g_ffh[FFELEM], g_ffl[FFELEM];
__device__ float g_tmp[NELEM];
__device__ float g_r1f[NELEM];
__device__ float g_tmp2[NELEM];

// ================= helpers ===================================================
__device__ __forceinline__ void split2(float a, float b, uint32_t& hi, uint32_t& lo) {
    __nv_bfloat16 ha = __float2bfloat16_rn(a);
    __nv_bfloat16 hb = __float2bfloat16_rn(b);
    float la = a - __bfloat162float(ha);
    float lb = b - __bfloat162float(hb);
    __nv_bfloat162 hv = __halves2bfloat162(ha, hb);
    __nv_bfloat162 lv = __floats2bfloat162_rn(la, lb);
    hi = *reinterpret_cast<uint32_t*>(&hv);
    lo = *reinterpret_cast<uint32_t*>(&lv);
}

#define CP16(dst, src) \
    asm volatile("cp.async.cg.shared.global [%0], [%1], 16;" :: \
        "r"((uint32_t)__cvta_generic_to_shared(dst)), "l"(src))
#define CP_COMMIT() asm volatile("cp.async.commit_group;" ::: "memory")
#define CP_WAIT(n)  asm volatile("cp.async.wait_group %0;" :: "n"(n) : "memory")

// ---------------- fp32 -> bf16 hi/lo conversion ------------------------------
__global__ __launch_bounds__(256)
void cvt_hl(const float* __restrict__ src, __nv_bfloat16* __restrict__ hi,
            __nv_bfloat16* __restrict__ lo, int n4)
{
    int i = blockIdx.x * 256 + threadIdx.x;
    if (i < n4) {
        float4 v = ((const float4*)src)[i];
        uint32_t h01, l01, h23, l23;
        split2(v.x, v.y, h01, l01);
        split2(v.z, v.w, h23, l23);
        ((uint2*)hi)[i] = make_uint2(h01, h23);
        ((uint2*)lo)[i] = make_uint2(l01, l23);
    }
}

// ================= WMMA GEMM: C = A @ B^T (+epilogue), bf16x3 ================
// k-chunk 32, 2-stage cp.async pipeline, 80KB smem -> 2 CTAs/SM.
// EPI: 0 none, 1 relu, 2 residual. OUT: 0 fp32, 1 bf16 hi/lo. QKV: fused 3-dest.
#define GLDT    40
#define GTILE   (128 * GLDT)                 // 5120 elems
#define GSTAGE  (4 * GTILE)                  // Ah,Al,Bh,Bl = 20480 elems
#define GSTAGES 2
#define GEMM_SMEM (GSTAGES * GSTAGE * 2)     // 81920 B

__device__ __forceinline__ void gemm_issue(__nv_bfloat16* st,
    const __nv_bfloat16* Ahg, const __nv_bfloat16* Alg,
    const __nv_bfloat16* Bhg, const __nv_bfloat16* Blg,
    int K, int k0, int tid)
{
    const __nv_bfloat16* srcs[4] = {Ahg, Alg, Bhg, Blg};
#pragma unroll
    for (int tile = 0; tile < 4; tile++) {
        __nv_bfloat16* dst = st + tile * GTILE;
        const __nv_bfloat16* g = srcs[tile];
#pragma unroll
        for (int it = 0; it < 2; it++) {
            int ch = tid + it * 256;          // 0..511
            int r = ch >> 2;                  // 0..127
            int c = (ch & 3) * 8;             // 0..24
            CP16(dst + r * GLDT + c, g + (size_t)r * K + k0 + c);
        }
    }
}

template <int EPI, int OUT, int QKV>
__global__ __launch_bounds__(256, 2)
void gemm_bf(const __nv_bfloat16* __restrict__ Ah, const __nv_bfloat16* __restrict__ Al,
             const __nv_bfloat16* __restrict__ Bh_, const __nv_bfloat16* __restrict__ Bl_,
             const __nv_bfloat16* __restrict__ Bh2, const __nv_bfloat16* __restrict__ Bl2,
             const __nv_bfloat16* __restrict__ Bh3, const __nv_bfloat16* __restrict__ Bl3,
             const float* __restrict__ Rf, float* __restrict__ Cf,
             __nv_bfloat16* __restrict__ Ch_, __nv_bfloat16* __restrict__ Cl_,
             __nv_bfloat16* __restrict__ Ch2, __nv_bfloat16* __restrict__ Cl2,
             __nv_bfloat16* __restrict__ Ch3, __nv_bfloat16* __restrict__ Cl3,
             int M, int N, int K)
{
    extern __shared__ __nv_bfloat16 sh[];

    const int tid = threadIdx.x;
    const int wid = tid >> 5;
    const int wm = (wid & 3) * 32;
    const int wn = (wid >> 2) * 64;

    const __nv_bfloat16* Bh = Bh_;
    const __nv_bfloat16* Bl = Bl_;
    __nv_bfloat16* Ch = Ch_;
    __nv_bfloat16* Cl = Cl_;
    int col0;
    if (QKV) {
        const int mat = blockIdx.x >> 3;      // 0,1,2 -> q,k,v
        col0 = (blockIdx.x & 7) * 128;
        if (mat == 1) { Bh = Bh2; Bl = Bl2; Ch = Ch2; Cl = Cl2; }
        else if (mat == 2) { Bh = Bh3; Bl = Bl3; Ch = Ch3; Cl = Cl3; }
    } else {
        col0 = blockIdx.x * 128;
    }
    const int row0 = blockIdx.y * 128;
    const __nv_bfloat16* Ahg = Ah + (size_t)row0 * K;
    const __nv_bfloat16* Alg = Al + (size_t)row0 * K;
    const __nv_bfloat16* Bhg = Bh + (size_t)col0 * K;
    const __nv_bfloat16* Blg = Bl + (size_t)col0 * K;

    wmma::fragment<wmma::accumulator, 16, 16, 16, float> acc[2][4];
#pragma unroll
    for (int i = 0; i < 2; i++)
#pragma unroll
        for (int j = 0; j < 4; j++) wmma::fill_fragment(acc[i][j], 0.f);

    const int T = K / 32;
    gemm_issue(sh, Ahg, Alg, Bhg, Blg, K, 0, tid);
    CP_COMMIT();

    for (int t = 0; t < T; t++) {
        CP_WAIT(0);
        __syncthreads();      // chunk t landed; all warps done with buf t-1 compute
        if (t + 1 < T) {
            gemm_issue(sh + ((t + 1) & 1) * GSTAGE, Ahg, Alg, Bhg, Blg,
                       K, (t + 1) * 32, tid);
            CP_COMMIT();
        }
        __nv_bfloat16* Ahs = sh + (t & 1) * GSTAGE;
        __nv_bfloat16* Als = Ahs + GTILE;
        __nv_bfloat16* Bhs = Ahs + 2 * GTILE;
        __nv_bfloat16* Bls = Ahs + 3 * GTILE;
#pragma unroll
        for (int ks = 0; ks < 32; ks += 16) {
            wmma::fragment<wmma::matrix_a, 16, 16, 16, __nv_bfloat16, wmma::row_major> a_hi[2], a_lo[2];
#pragma unroll
            for (int i = 0; i < 2; i++) {
                wmma::load_matrix_sync(a_hi[i], Ahs + (wm + i * 16) * GLDT + ks, GLDT);
                wmma::load_matrix_sync(a_lo[i], Als + (wm + i * 16) * GLDT + ks, GLDT);
            }
#pragma unroll
            for (int j = 0; j < 4; j++) {
                wmma::fragment<wmma::matrix_b, 16, 16, 16, __nv_bfloat16, wmma::col_major> b_hi, b_lo;
                wmma::load_matrix_sync(b_hi, Bhs + (wn + j * 16) * GLDT + ks, GLDT);
                wmma::load_matrix_sync(b_lo, Bls + (wn + j * 16) * GLDT + ks, GLDT);
#pragma unroll
                for (int i = 0; i < 2; i++) {
                    wmma::mma_sync(acc[i][j], a_hi[i], b_hi, acc[i][j]);
                    wmma::mma_sync(acc[i][j], a_hi[i], b_lo, acc[i][j]);
                    wmma::mma_sync(acc[i][j], a_lo[i], b_hi, acc[i][j]);
                }
            }
        }
        __syncthreads();      // compute done before buf t gets overwritten at t+2
    }

    if (OUT == 0) {
#pragma unroll
        for (int i = 0; i < 2; i++) {
#pragma unroll
            for (int j = 0; j < 4; j++) {
                const int row = row0 + wm + i * 16;
                const int col = col0 + wn + j * 16;
                if (EPI == 2) {
                    wmma::fragment<wmma::accumulator, 16, 16, 16, float> rf;
                    wmma::load_matrix_sync(rf, Rf + (size_t)row * N + col, N, wmma::mem_row_major);
#pragma unroll
                    for (int e = 0; e < rf.num_elements; e++) acc[i][j].x[e] += rf.x[e];
                }
                if (EPI == 1) {
#pragma unroll
                    for (int e = 0; e < acc[i][j].num_elements; e++)
                        acc[i][j].x[e] = fmaxf(acc[i][j].x[e], 0.f);
                }
                wmma::store_matrix_sync(Cf + (size_t)row * N + col, acc[i][j], N, wmma::mem_row_major);
            }
        }
    } else {
        float* stg = (float*)sh;              // 128 x 132 fp32 staging (67584 B < 81920)
        __syncthreads();
#pragma unroll
        for (int i = 0; i < 2; i++) {
#pragma unroll
            for (int j = 0; j < 4; j++) {
                if (EPI == 1) {
#pragma unroll
                    for (int e = 0; e < acc[i][j].num_elements; e++)
                        acc[i][j].x[e] = fmaxf(acc[i][j].x[e], 0.f);
                }
                wmma::store_matrix_sync(stg + (wm + i * 16) * 132 + wn + j * 16,
                                        acc[i][j], 132, wmma::mem_row_major);
            }
        }
        __syncthreads();
        const int r = tid >> 1;
        const int cb = (tid & 1) * 64;
#pragma unroll
        for (int j = 0; j < 64; j += 4) {
            float4 v = *(const float4*)(stg + r * 132 + cb + j);
            uint32_t h01, l01, h23, l23;
            split2(v.x, v.y, h01, l01);
            split2(v.z, v.w, h23, l23);
            const size_t off = (size_t)(row0 + r) * N + col0 + cb + j;
            *(uint2*)(Ch + off) = make_uint2(h01, h23);
            *(uint2*)(Cl + off) = make_uint2(l01, l23);
        }
    }
}

// ================= WMMA flash attention (bf16x3 in/out, fp32 softmax) ========
#define LDH 72
#define LDF 68
#define FO_QH 0
#define FO_QL (FO_QH + 128 * LDH * 2)
#define FO_KH (FO_QL + 128 * LDH * 2)
#define FO_KL (FO_KH + 64 * LDH * 2)
#define FO_VH (FO_KL + 64 * LDH * 2)
#define FO_VL (FO_VH + 64 * LDH * 2)
#define FO_PH (FO_VL + 64 * LDH * 2)
#define FO_PL (FO_PH + 128 * LDH * 2)
#define FO_SF (FO_PL + 128 * LDH * 2)
#define FO_MR (FO_SF + 128 * LDF * 4)
#define FO_LR (FO_MR + 512)
#define FO_CR (FO_LR + 512)
#define FA_SMEM (FO_CR + 512)             // 146944 B

__global__ __launch_bounds__(512)
void flash_bf(const __nv_bfloat16* __restrict__ Qh_g, const __nv_bfloat16* __restrict__ Ql_g,
              const __nv_bfloat16* __restrict__ Kh_g, const __nv_bfloat16* __restrict__ Kl_g,
              const __nv_bfloat16* __restrict__ Vh_g, const __nv_bfloat16* __restrict__ Vl_g,
              __nv_bfloat16* __restrict__ Oh_g, __nv_bfloat16* __restrict__ Ol_g)
{
    extern __shared__ char fsm[];
    __nv_bfloat16* Qh = (__nv_bfloat16*)(fsm + FO_QH);
    __nv_bfloat16* Ql = (__nv_bfloat16*)(fsm + FO_QL);
    __nv_bfloat16* Kh = (__nv_bfloat16*)(fsm + FO_KH);
    __nv_bfloat16* Kl = (__nv_bfloat16*)(fsm + FO_KL);
    __nv_bfloat16* Vh = (__nv_bfloat16*)(fsm + FO_VH);
    __nv_bfloat16* Vl = (__nv_bfloat16*)(fsm + FO_VL);
    __nv_bfloat16* Ph = (__nv_bfloat16*)(fsm + FO_PH);
    __nv_bfloat16* Pl = (__nv_bfloat16*)(fsm + FO_PL);
    float* Sf   = (float*)(fsm + FO_SF);
    float* mrow = (float*)(fsm + FO_MR);
    float* lrow = (float*)(fsm + FO_LR);
    float* crow = (float*)(fsm + FO_CR);

    const int qb = gridDim.x - 1 - blockIdx.x;   // heavy q-blocks first
    const int h = blockIdx.y, bb = blockIdx.z;
    const int tid = threadIdx.x;
    const int wid = tid >> 5;
    const int wm = (wid & 3) * 32;
    const int wn = (wid >> 2) * 16;
    const int q0 = qb * 128;
    const size_t base = (size_t)bb * SEQ * D_MODEL + (size_t)h * DKH;

    const int r  = tid >> 2;
    const int c0 = (tid & 3) * 16;

    {
        const size_t g = base + (size_t)(q0 + r) * D_MODEL + c0;
        *(uint4*)(Qh + r * LDH + c0)     = *(const uint4*)(Qh_g + g);
        *(uint4*)(Qh + r * LDH + c0 + 8) = *(const uint4*)(Qh_g + g + 8);
        *(uint4*)(Ql + r * LDH + c0)     = *(const uint4*)(Ql_g + g);
        *(uint4*)(Ql + r * LDH + c0 + 8) = *(const uint4*)(Ql_g + g + 8);
    }
    if (tid < 128) { mrow[tid] = -INFINITY; lrow[tid] = 0.f; }

    float orow[16];
#pragma unroll
    for (int j = 0; j < 16; j++) orow[j] = 0.f;
    __syncthreads();

    const int kmax = 2 * qb + 1;
    for (int kb = 0; kb <= kmax; kb++) {
        const int k0 = kb * 64;

        {
            const int kr = tid >> 3;
            const int kc = (tid & 7) * 8;
            const size_t g = base + (size_t)(k0 + kr) * D_MODEL + kc;
            *(uint4*)(Kh + kr * LDH + kc) = *(const uint4*)(Kh_g + g);
            *(uint4*)(Kl + kr * LDH + kc) = *(const uint4*)(Kl_g + g);
            *(uint4*)(Vh + kr * LDH + kc) = *(const uint4*)(Vh_g + g);
            *(uint4*)(Vl + kr * LDH + kc) = *(const uint4*)(Vl_g + g);
        }
        __syncthreads();

        {
            wmma::fragment<wmma::accumulator, 16, 16, 16, float> accS[2];
#pragma unroll
            for (int i = 0; i < 2; i++) wmma::fill_fragment(accS[i], 0.f);
#pragma unroll
            for (int ks = 0; ks < 64; ks += 16) {
                wmma::fragment<wmma::matrix_a, 16, 16, 16, __nv_bfloat16, wmma::row_major> ah[2], al[2];
                wmma::fragment<wmma::matrix_b, 16, 16, 16, __nv_bfloat16, wmma::col_major> bh, bl;
#pragma unroll
                for (int i = 0; i < 2; i++) {
                    wmma::load_matrix_sync(ah[i], Qh + (wm + i * 16) * LDH + ks, LDH);
                    wmma::load_matrix_sync(al[i], Ql + (wm + i * 16) * LDH + ks, LDH);
                }
                wmma::load_matrix_sync(bh, Kh + wn * LDH + ks, LDH);
                wmma::load_matrix_sync(bl, Kl + wn * LDH + ks, LDH);
#pragma unroll
                for (int i = 0; i < 2; i++) {
                    wmma::mma_sync(accS[i], ah[i], bh, accS[i]);
                    wmma::mma_sync(accS[i], ah[i], bl, accS[i]);
                    wmma::mma_sync(accS[i], al[i], bh, accS[i]);
                }
            }
#pragma unroll
            for (int i = 0; i < 2; i++)
                wmma::store_matrix_sync(Sf + (wm + i * 16) * LDF + wn, accS[i], LDF, wmma::mem_row_major);
        }
        __syncthreads();

        {
            const bool needmask = (k0 + 63 > q0);
            const int qrow = q0 + r;
            float sv[16];
            const float* srow = Sf + r * LDF + c0;
            float mx = -INFINITY;
#pragma unroll
            for (int j = 0; j < 16; j++) {
                float v = srow[j] * 0.125f;
                if (needmask && (k0 + c0 + j) > qrow) v = -INFINITY;
                sv[j] = v;
                mx = fmaxf(mx, v);
            }
            mx = fmaxf(mx, __shfl_xor_sync(0xFFFFFFFFu, mx, 1));
            mx = fmaxf(mx, __shfl_xor_sync(0xFFFFFFFFu, mx, 2));
            const float mold = mrow[r];
            const float mnew = fmaxf(mold, mx);
            float lsum = 0.f;
#pragma unroll
            for (int j = 0; j < 16; j++) {
                float p = __expf(sv[j] - mnew);
                sv[j] = p;
                lsum += p;
            }
            lsum += __shfl_xor_sync(0xFFFFFFFFu, lsum, 1);
            lsum += __shfl_xor_sync(0xFFFFFFFFu, lsum, 2);
#pragma unroll
            for (int j = 0; j < 16; j += 2) {
                uint32_t hv, lv;
                split2(sv[j], sv[j + 1], hv, lv);
                *(uint32_t*)(Ph + r * LDH + c0 + j) = hv;
                *(uint32_t*)(Pl + r * LDH + c0 + j) = lv;
            }
            if ((tid & 3) == 0) {
                const float corr = __expf(mold - mnew);
                mrow[r] = mnew;
                lrow[r] = lrow[r] * corr + lsum;
                crow[r] = corr;
            }
        }
        __syncthreads();

        {
            wmma::fragment<wmma::accumulator, 16, 16, 16, float> accO[2];
#pragma unroll
            for (int i = 0; i < 2; i++) wmma::fill_fragment(accO[i], 0.f);
#pragma unroll
            for (int ks = 0; ks < 64; ks += 16) {
                wmma::fragment<wmma::matrix_a, 16, 16, 16, __nv_bfloat16, wmma::row_major> ah[2], al[2];
                wmma::fragment<wmma::matrix_b, 16, 16, 16, __nv_bfloat16, wmma::row_major> bh, bl;
#pragma unroll
                for (int i = 0; i < 2; i++) {
                    wmma::load_matrix_sync(ah[i], Ph + (wm + i * 16) * LDH + ks, LDH);
                    wmma::load_matrix_sync(al[i], Pl + (wm + i * 16) * LDH + ks, LDH);
                }
                wmma::load_matrix_sync(bh, Vh + ks * LDH + wn, LDH);
                wmma::load_matrix_sync(bl, Vl + ks * LDH + wn, LDH);
#pragma unroll
                for (int i = 0; i < 2; i++) {
                    wmma::mma_sync(accO[i], ah[i], bh, accO[i]);
                    wmma::mma_sync(accO[i], ah[i], bl, accO[i]);
                    wmma::mma_sync(accO[i], al[i], bh, accO[i]);
                }
            }
#pragma unroll
            for (int i = 0; i < 2; i++)
                wmma::store_matrix_sync(Sf + (wm + i * 16) * LDF + wn, accO[i], LDF, wmma::mem_row_major);
        }
        __syncthreads();

        {
            const float corr = crow[r];
            const float* prow = Sf + r * LDF + c0;
#pragma unroll
            for (int j = 0; j < 16; j++) orow[j] = orow[j] * corr + prow[j];
        }
        __syncthreads();
    }

    {
        const float inv = 1.f / lrow[r];
        const size_t g = base + (size_t)(q0 + r) * D_MODEL + c0;
#pragma unroll
        for (int j = 0; j < 16; j += 2) {
            uint32_t hv, lv;
            split2(orow[j] * inv, orow[j + 1] * inv, hv, lv);
            *(uint32_t*)(Oh_g + g + j) = hv;
            *(uint32_t*)(Ol_g + g + j) = lv;
        }
    }
}

// ---------------- LayerNorm (ddof=1), optional hi/lo output ------------------
template <bool HL>
__global__ __launch_bounds__(256)
void layernorm_k(const float* __restrict__ in, const float* __restrict__ gamma,
                 const float* __restrict__ beta, float* __restrict__ out,
                 __nv_bfloat16* __restrict__ oh, __nv_bfloat16* __restrict__ ol)
{
    const int row = blockIdx.x;
    const int tid = threadIdx.x;
    const float4 v = ((const float4*)(in + (size_t)row * D_MODEL))[tid];
    float s  = v.x + v.y + v.z + v.w;
    float ss = v.x * v.x + v.y * v.y + v.z * v.z + v.w * v.w;

    __shared__ float rs[8], rss[8];
#pragma unroll
    for (int o = 16; o > 0; o >>= 1) {
        s  += __shfl_down_sync(0xFFFFFFFFu, s, o);
        ss += __shfl_down_sync(0xFFFFFFFFu, ss, o);
    }
    if ((tid & 31) == 0) { rs[tid >> 5] = s; rss[tid >> 5] = ss; }
    __syncthreads();
    float S = 0.f, SS = 0.f;
#pragma unroll
    for (int i = 0; i < 8; i++) { S += rs[i]; SS += rss[i]; }

    const float mean = S * (1.f / (float)D_MODEL);
    const float var  = (SS - (float)D_MODEL * mean * mean) * (1.f / (float)(D_MODEL - 1));
    const float inv  = rsqrtf(var + EPS_LN);

    const float4 g = ((const float4*)gamma)[tid];
    const float4 b = ((const float4*)beta)[tid];
    float4 o;
    o.x = g.x * (v.x - mean) * inv + b.x;
    o.y = g.y * (v.y - mean) * inv + b.y;
    o.z = g.z * (v.z - mean) * inv + b.z;
    o.w = g.w * (v.w - mean) * inv + b.w;
    ((float4*)(out + (size_t)row * D_MODEL))[tid] = o;
    if (HL) {
        uint32_t h01, l01, h23, l23;
        split2(o.x, o.y, h01, l01);
        split2(o.z, o.w, h23, l23);
        ((uint2*)(oh + (size_t)row * D_MODEL))[tid] = make_uint2(h01, h23);
        ((uint2*)(ol + (size_t)row * D_MODEL))[tid] = make_uint2(l01, l23);
    }
}

// ---------------- host launcher ---------------------------------------------
extern "C" void kernel_launch(void* const* d_in, const int* in_sizes, int n_in,
                              void* d_out, int out_size)
{
    (void)in_sizes; (void)n_in; (void)out_size;
    const float* x  = (const float*)d_in[0];
    const float* Wq = (const float*)d_in[2];
    const float* Wk = (const float*)d_in[3];
    const float* Wv = (const float*)d_in[4];
    const float* Wo = (const float*)d_in[5];
    const float* W1 = (const float*)d_in[6];
    const float* W2 = (const float*)d_in[7];
    const float* g1 = (const float*)d_in[8];
    const float* b1 = (const float*)d_in[9];
    const float* g2 = (const float*)d_in[10];
    const float* b2 = (const float*)d_in[11];
    float* out = (float*)d_out;

    __nv_bfloat16 *xh, *xl, *wqh, *wql, *wkh, *wkl, *wvh, *wvl, *woh, *wol;
    __nv_bfloat16 *w1h, *w1l, *w2h, *w2l;
    __nv_bfloat16 *qh, *ql, *kh, *kl, *vh, *vl, *ah, *al, *r1h, *r1l, *ffh, *ffl;
    float *tmp, *r1f, *tmp2;
    cudaGetSymbolAddress((void**)&xh, g_xh);   cudaGetSymbolAddress((void**)&xl, g_xl);
    cudaGetSymbolAddress((void**)&wqh, g_wqh); cudaGetSymbolAddress((void**)&wql, g_wql);
    cudaGetSymbolAddress((void**)&wkh, g_wkh); cudaGetSymbolAddress((void**)&wkl, g_wkl);
    cudaGetSymbolAddress((void**)&wvh, g_wvh); cudaGetSymbolAddress((void**)&wvl, g_wvl);
    cudaGetSymbolAddress((void**)&woh, g_woh); cudaGetSymbolAddress((void**)&wol, g_wol);
    cudaGetSymbolAddress((void**)&w1h, g_w1h); cudaGetSymbolAddress((void**)&w1l, g_w1l);
    cudaGetSymbolAddress((void**)&w2h, g_w2h); cudaGetSymbolAddress((void**)&w2l, g_w2l);
    cudaGetSymbolAddress((void**)&qh, g_qh);   cudaGetSymbolAddress((void**)&ql, g_ql);
    cudaGetSymbolAddress((void**)&kh, g_kh);   cudaGetSymbolAddress((void**)&kl, g_kl);
    cudaGetSymbolAddress((void**)&vh, g_vh);   cudaGetSymbolAddress((void**)&vl, g_vl);
    cudaGetSymbolAddress((void**)&ah, g_ah);   cudaGetSymbolAddress((void**)&al, g_al);
    cudaGetSymbolAddress((void**)&r1h, g_r1h); cudaGetSymbolAddress((void**)&r1l, g_r1l);
    cudaGetSymbolAddress((void**)&ffh, g_ffh); cudaGetSymbolAddress((void**)&ffl, g_ffl);
    cudaGetSymbolAddress((void**)&tmp, g_tmp);
    cudaGetSymbolAddress((void**)&r1f, g_r1f);
    cudaGetSymbolAddress((void**)&tmp2, g_tmp2);

    cudaFuncSetAttribute(gemm_bf<0,1,1>, cudaFuncAttributeMaxDynamicSharedMemorySize, GEMM_SMEM);
    cudaFuncSetAttribute(gemm_bf<1,1,0>, cudaFuncAttributeMaxDynamicSharedMemorySize, GEMM_SMEM);
    cudaFuncSetAttribute(gemm_bf<2,0,0>, cudaFuncAttributeMaxDynamicSharedMemorySize, GEMM_SMEM);
    cudaFuncSetAttribute(flash_bf, cudaFuncAttributeMaxDynamicSharedMemorySize, FA_SMEM);

    const dim3 blk(256);

    // ---- conversion passes ----
    cvt_hl<<<NELEM / 4 / 256, blk>>>(x,  xh,  xl,  NELEM / 4);
    cvt_hl<<<WELEM / 4 / 256, blk>>>(Wq, wqh, wql, WELEM / 4);
    cvt_hl<<<WELEM / 4 / 256, blk>>>(Wk, wkh, wkl, WELEM / 4);
    cvt_hl<<<WELEM / 4 / 256, blk>>>(Wv, wvh, wvl, WELEM / 4);
    cvt_hl<<<WELEM / 4 / 256, blk>>>(Wo, woh, wol, WELEM / 4);
    cvt_hl<<<FELEM / 4 / 256, blk>>>(W1, w1h, w1l, FELEM / 4);
    cvt_hl<<<FELEM / 4 / 256, blk>>>(W2, w2h, w2l, FELEM / 4);

    const dim3 gQKV(24, MROWS / 128);            // fused QKV
    const dim3 gD(D_MODEL / 128, MROWS / 128);   // (8, 32)
    const dim3 gF(D_FF / 128, MROWS / 128);      // (32, 32)

    // Fused QKV projection -> bf16 hi/lo
    gemm_bf<0,1,1><<<gQKV, blk, GEMM_SMEM>>>(xh, xl, wqh, wql, wkh, wkl, wvh, wvl,
                                             nullptr, nullptr, qh, ql, kh, kl, vh, vl,
                                             MROWS, D_MODEL, D_MODEL);

    // Flash attention (bf16 in/out)
    flash_bf<<<dim3(SEQ / 128, HEADS, BATCH), dim3(512), FA_SMEM>>>(qh, ql, kh, kl, vh, vl, ah, al);

    // Output projection + residual x -> fp32, then LN1 (fp32 + hi/lo)
    gemm_bf<2,0,0><<<gD, blk, GEMM_SMEM>>>(ah, al, woh, wol, nullptr, nullptr, nullptr, nullptr,
                                           x, tmp, nullptr, nullptr, nullptr, nullptr, nullptr, nullptr,
                                           MROWS, D_MODEL, D_MODEL);
    layernorm_k<true><<<MROWS, blk>>>(tmp, g1, b1, r1f, r1h, r1l);

    // FFN
    gemm_bf<1,1,0><<<gF, blk, GEMM_SMEM>>>(r1h, r1l, w1h, w1l, nullptr, nullptr, nullptr, nullptr,
                                           nullptr, nullptr, ffh, ffl, nullptr, nullptr, nullptr, nullptr,
                                           MROWS, D_FF, D_MODEL);
    gemm_bf<2,0,0><<<gD, blk, GEMM_SMEM>>>(ffh, ffl, w2h, w2l, nullptr, nullptr, nullptr, nullptr,
                                           r1f, tmp2, nullptr, nullptr, nullptr, nullptr, nullptr, nullptr,
                                           MROWS, D_MODEL, D_FF);
    layernorm_k<false><<<MROWS, blk>>>(tmp2, g2, b2, out, nullptr, nullptr);
}